// round 3
// baseline (speedup 1.0000x reference)
#include <cuda_runtime.h>
#include <math.h>

// Problem constants
#define Bz 32
#define Tz 64
#define Vz 50257
#define Ez 256
#define Hz 512
#define GATES 2048          // 4*H
#define Mz 2048             // T*B
#define K2 1024             // 2*H

// Scratch (static device allocations are allowed; runtime allocs are not)
__device__ float g_xseq[Mz * Ez];        // 2 MB   gathered shifted embeddings [t*B+b][E]
__device__ float g_hgates[Bz * GATES];   // 256 KB features @ W_hh^T + b_ih + b_hh
__device__ float g_gates[(size_t)Mz * GATES];   // 16 MB gate pre-activations
__device__ float g_hs[(size_t)Mz * Hz];  // 4 MB   LSTM hidden states [t*B+b][H]
__device__ float g_hid[(size_t)Mz * K2]; // 8 MB   hs @ W1^T + b1

// ---------------------------------------------------------------------------
// Kernel 1: gather shifted caption embeddings.
// x_seq[t][b] = emb[captions[b][ t==0 ? 0 : t-1 ]]
// ---------------------------------------------------------------------------
__global__ void gather_kernel(const int* __restrict__ captions,
                              const float* __restrict__ emb)
{
    int m = blockIdx.x;           // 0..2047
    int t = m / Bz;
    int b = m % Bz;
    int src_t = (t == 0) ? 0 : (t - 1);
    int token = captions[b * Tz + src_t];
    const float4* src = (const float4*)(emb + (size_t)token * Ez);
    float4* dst = (float4*)(g_xseq + (size_t)m * Ez);
    dst[threadIdx.x] = src[threadIdx.x];
}

// ---------------------------------------------------------------------------
// Kernel 2: h_gates[b][g] = sum_k features[b][k]*W_hh[g][k] + b_ih[g] + b_hh[g]
// ---------------------------------------------------------------------------
__global__ void hgates_kernel(const float* __restrict__ features,
                              const float* __restrict__ W_hh,
                              const float* __restrict__ b_ih,
                              const float* __restrict__ b_hh)
{
    int idx = blockIdx.x * blockDim.x + threadIdx.x;  // 0..65535
    if (idx >= Bz * GATES) return;
    int b = idx / GATES;
    int g = idx % GATES;
    const float4* w = (const float4*)(W_hh + (size_t)g * Hz);
    const float4* f = (const float4*)(features + (size_t)b * Hz);
    float s = b_ih[g] + b_hh[g];
    #pragma unroll 4
    for (int k = 0; k < Hz / 4; k++) {
        float4 wv = w[k];
        float4 fv = f[k];
        s += fv.x * wv.x + fv.y * wv.y + fv.z * wv.z + fv.w * wv.w;
    }
    g_hgates[idx] = s;
}

// ---------------------------------------------------------------------------
// Kernel 3: elementwise LSTM scan. Only cell state c carries across t.
// Gate order (jnp.split): i=[0:H), f=[H:2H), g=[2H:3H), o=[3H:4H)
// ---------------------------------------------------------------------------
__global__ void scan_kernel()
{
    int idx = blockIdx.x * blockDim.x + threadIdx.x;  // 0..16383
    if (idx >= Bz * Hz) return;
    int b = idx >> 9;        // /512
    int h = idx & (Hz - 1);
    float c = 0.f;
    for (int t = 0; t < Tz; t++) {
        const float* g = g_gates + (size_t)(t * Bz + b) * GATES;
        float gi = g[h];
        float gf = g[h + Hz];
        float gg = g[h + 2 * Hz];
        float go = g[h + 3 * Hz];
        float si = 1.f / (1.f + expf(-gi));
        float sf = 1.f / (1.f + expf(-gf));
        float so = 1.f / (1.f + expf(-go));
        c = sf * c + si * tanhf(gg);
        g_hs[(size_t)(t * Bz + b) * Hz + h] = so * tanhf(c);
    }
}

// ---------------------------------------------------------------------------
// Shared SIMT GEMM (NT): C[m][n] = dot(A[m,:], Bm[n,:]) + epilogue
// 128x128 block tile, BK=8, 256 threads, 8x8 register tile.
// MODE 0: A=g_xseq (K=256),  C=g_gates, epi += g_hgates[(m%32)][n]
// MODE 1: A=g_hs   (K=512),  C=g_hid,   epi += b1[n]
// MODE 2: A=g_hid  (K=1024), C=out[(b)(t)][v] (row base NOT 16B-aligned ->
//         scalar stores only!)
// ---------------------------------------------------------------------------
#define BM 128
#define BN 128
#define BKq 8
#define TM 8
#define TN 8

template <int MODE>
__global__ void __launch_bounds__(256)
gemm_nt_kernel(const float* __restrict__ Bm,
               const float* __restrict__ bias,
               float* __restrict__ Cout,   // used only for MODE 2
               int M, int N, int K)
{
    __shared__ float As[BKq][BM];
    __shared__ float Bs[BKq][BN];

    const float* A = (MODE == 0) ? g_xseq : (MODE == 1) ? g_hs : g_hid;

    int block_m = blockIdx.y * BM;
    int block_n = blockIdx.x * BN;
    int tid = threadIdx.x;

    int lr = tid >> 1;            // 0..127: row within tile for loads
    int lk = (tid & 1) * 4;       // 0 or 4: k-offset for float4 load

    const float* Aptr = A + (size_t)(block_m + lr) * K + lk;
    bool bvalid = (block_n + lr) < N;
    const float* Bptr = Bm + (size_t)(bvalid ? (block_n + lr) : 0) * K + lk;

    float acc[TM][TN];
    #pragma unroll
    for (int i = 0; i < TM; i++)
        #pragma unroll
        for (int j = 0; j < TN; j++) acc[i][j] = 0.f;

    int tx = tid & 15;            // 0..15 -> n sub-tile
    int ty = tid >> 4;            // 0..15 -> m sub-tile

    for (int k0 = 0; k0 < K; k0 += BKq) {
        float4 av = *(const float4*)Aptr;
        float4 bv = bvalid ? *(const float4*)Bptr : make_float4(0.f, 0.f, 0.f, 0.f);
        __syncthreads();
        As[lk + 0][lr] = av.x; As[lk + 1][lr] = av.y;
        As[lk + 2][lr] = av.z; As[lk + 3][lr] = av.w;
        Bs[lk + 0][lr] = bv.x; Bs[lk + 1][lr] = bv.y;
        Bs[lk + 2][lr] = bv.z; Bs[lk + 3][lr] = bv.w;
        __syncthreads();

        #pragma unroll
        for (int kk = 0; kk < BKq; kk++) {
            float a[TM], b[TN];
            const float4* ap = (const float4*)&As[kk][ty * TM];
            const float4* bp = (const float4*)&Bs[kk][tx * TN];
            float4 a0 = ap[0], a1 = ap[1];
            float4 b0 = bp[0], b1v = bp[1];
            a[0]=a0.x; a[1]=a0.y; a[2]=a0.z; a[3]=a0.w;
            a[4]=a1.x; a[5]=a1.y; a[6]=a1.z; a[7]=a1.w;
            b[0]=b0.x; b[1]=b0.y; b[2]=b0.z; b[3]=b0.w;
            b[4]=b1v.x; b[5]=b1v.y; b[6]=b1v.z; b[7]=b1v.w;
            #pragma unroll
            for (int i = 0; i < TM; i++)
                #pragma unroll
                for (int j = 0; j < TN; j++)
                    acc[i][j] += a[i] * b[j];
        }
        Aptr += BKq;
        Bptr += BKq;
    }

    // Epilogue
    int n0 = block_n + tx * TN;
    #pragma unroll
    for (int i = 0; i < TM; i++) {
        int m = block_m + ty * TM + i;
        float v[TN];
        #pragma unroll
        for (int j = 0; j < TN; j++) {
            float x = acc[i][j];
            int n = n0 + j;
            if (MODE == 0) {
                if (n < N) x += g_hgates[(size_t)(m & (Bz - 1)) * GATES + n];
            } else {
                if (n < N) x += bias[n];
            }
            v[j] = x;
        }
        if (MODE == 0) {
            float* dst = g_gates + (size_t)m * GATES + n0;
            ((float4*)dst)[0] = make_float4(v[0], v[1], v[2], v[3]);
            ((float4*)dst)[1] = make_float4(v[4], v[5], v[6], v[7]);
        } else if (MODE == 1) {
            float* dst = g_hid + (size_t)m * K2 + n0;
            ((float4*)dst)[0] = make_float4(v[0], v[1], v[2], v[3]);
            ((float4*)dst)[1] = make_float4(v[4], v[5], v[6], v[7]);
        } else {
            // Vz is odd -> logits rows are not 16B aligned. Scalar stores.
            int bb = m & (Bz - 1);
            int tt = m >> 5;
            float* dst = Cout + ((size_t)bb * Tz + tt) * Vz + n0;
            #pragma unroll
            for (int j = 0; j < TN; j++)
                if (n0 + j < N) dst[j] = v[j];
        }
    }
}

// ---------------------------------------------------------------------------
// Launch
// ---------------------------------------------------------------------------
extern "C" void kernel_launch(void* const* d_in, const int* in_sizes, int n_in,
                              void* d_out, int out_size)
{
    const float* features = (const float*)d_in[0];
    const int*   captions = (const int*)d_in[1];
    const float* emb      = (const float*)d_in[2];
    const float* W_ih     = (const float*)d_in[3];
    const float* W_hh     = (const float*)d_in[4];
    const float* b_ih     = (const float*)d_in[5];
    const float* b_hh     = (const float*)d_in[6];
    const float* W1       = (const float*)d_in[7];
    const float* b1       = (const float*)d_in[8];
    const float* W2       = (const float*)d_in[9];
    const float* b2       = (const float*)d_in[10];
    float* out = (float*)d_out;

    // 1) gather shifted embeddings
    gather_kernel<<<Mz, Ez / 4>>>(captions, emb);

    // 2) h_gates (+ both biases)
    hgates_kernel<<<(Bz * GATES + 255) / 256, 256>>>(features, W_hh, b_ih, b_hh);

    // 3) gates GEMM: (2048 x 2048 x 256), epilogue adds h_gates
    {
        dim3 grid((GATES + BN - 1) / BN, Mz / BM);
        gemm_nt_kernel<0><<<grid, 256>>>(W_ih, nullptr, nullptr, Mz, GATES, Ez);
    }

    // 4) elementwise LSTM scan
    scan_kernel<<<(Bz * Hz + 255) / 256, 256>>>();

    // 5) hid GEMM: (2048 x 1024 x 512) + b1
    {
        dim3 grid((K2 + BN - 1) / BN, Mz / BM);
        gemm_nt_kernel<1><<<grid, 256>>>(W1, b1, nullptr, Mz, K2, Hz);
    }

    // 6) logits GEMM: (2048 x 50257 x 1024) + b2 -> out[b][t][v]
    {
        dim3 grid((Vz + BN - 1) / BN, Mz / BM);
        gemm_nt_kernel<2><<<grid, 256>>>(W2, b2, out, Mz, Vz, K2);
    }
}

// round 5
// speedup vs baseline: 2.0750x; 2.0750x over previous
#include <cuda_runtime.h>
#include <cuda_bf16.h>
#include <math.h>
#include <stdint.h>

// Problem constants
#define Bz 32
#define Tz 64
#define Vz 50257
#define Ez 256
#define Hz 512
#define GATES 2048          // 4*H
#define Mz 2048             // T*B
#define K2 1024             // 2*H

// ---------------------------------------------------------------------------
// Scratch (static device allocations only)
// ---------------------------------------------------------------------------
__device__ float g_xseq[Mz * Ez];
__device__ float g_hgates[Bz * GATES];
__device__ float g_gates[(size_t)Mz * GATES];
__device__ float g_hs[(size_t)Mz * Hz];
__device__ float g_hid[(size_t)Mz * K2];

// bf16 split operands for the tensor-core logits GEMM
__device__ __nv_bfloat16 g_w2hi[(size_t)Vz * K2];   // ~103 MB
__device__ __nv_bfloat16 g_w2lo[(size_t)Vz * K2];   // ~103 MB
__device__ __nv_bfloat16 g_hidhi[(size_t)Mz * K2];  // 4 MB
__device__ __nv_bfloat16 g_hidlo[(size_t)Mz * K2];  // 4 MB

// ---------------------------------------------------------------------------
// PTX helpers (base PTX only — NO tcgen05; harness assembles for sm_103 base)
// ---------------------------------------------------------------------------
__device__ __forceinline__ uint32_t smem_u32(const void* p) {
    uint32_t a;
    asm("{ .reg .u64 t; cvta.to.shared.u64 t, %1; cvt.u32.u64 %0, t; }"
        : "=r"(a) : "l"(p));
    return a;
}
#define CP16(dst, src) \
    asm volatile("cp.async.cg.shared.global [%0], [%1], 16;" :: "r"(dst), "l"(src) : "memory")
#define CP_COMMIT()  asm volatile("cp.async.commit_group;" ::: "memory")
#define CP_WAIT(n)   asm volatile("cp.async.wait_group %0;" :: "n"(n) : "memory")

__device__ __forceinline__ void ldsm4(uint32_t* r, uint32_t addr) {
    asm volatile("ldmatrix.sync.aligned.m8n8.x4.shared.b16 {%0,%1,%2,%3}, [%4];"
                 : "=r"(r[0]), "=r"(r[1]), "=r"(r[2]), "=r"(r[3]) : "r"(addr));
}
__device__ __forceinline__ void mma16816(float* c, const uint32_t* a, const uint32_t* b) {
    asm volatile("mma.sync.aligned.m16n8k16.row.col.f32.bf16.bf16.f32 "
                 "{%0,%1,%2,%3}, {%4,%5,%6,%7}, {%8,%9}, {%0,%1,%2,%3};"
                 : "+f"(c[0]), "+f"(c[1]), "+f"(c[2]), "+f"(c[3])
                 : "r"(a[0]), "r"(a[1]), "r"(a[2]), "r"(a[3]),
                   "r"(b[0]), "r"(b[1]));
}

// ---------------------------------------------------------------------------
// Kernel 1: gather shifted caption embeddings.
// ---------------------------------------------------------------------------
__global__ void gather_kernel(const int* __restrict__ captions,
                              const float* __restrict__ emb)
{
    int m = blockIdx.x;
    int t = m / Bz;
    int b = m % Bz;
    int src_t = (t == 0) ? 0 : (t - 1);
    int token = captions[b * Tz + src_t];
    const float4* src = (const float4*)(emb + (size_t)token * Ez);
    float4* dst = (float4*)(g_xseq + (size_t)m * Ez);
    dst[threadIdx.x] = src[threadIdx.x];
}

// ---------------------------------------------------------------------------
// Kernel 2: h_gates
// ---------------------------------------------------------------------------
__global__ void hgates_kernel(const float* __restrict__ features,
                              const float* __restrict__ W_hh,
                              const float* __restrict__ b_ih,
                              const float* __restrict__ b_hh)
{
    int idx = blockIdx.x * blockDim.x + threadIdx.x;
    if (idx >= Bz * GATES) return;
    int b = idx / GATES;
    int g = idx % GATES;
    const float4* w = (const float4*)(W_hh + (size_t)g * Hz);
    const float4* f = (const float4*)(features + (size_t)b * Hz);
    float s = b_ih[g] + b_hh[g];
    #pragma unroll 4
    for (int k = 0; k < Hz / 4; k++) {
        float4 wv = w[k];
        float4 fv = f[k];
        s += fv.x * wv.x + fv.y * wv.y + fv.z * wv.z + fv.w * wv.w;
    }
    g_hgates[idx] = s;
}

// ---------------------------------------------------------------------------
// Kernel 3: elementwise LSTM scan.
// ---------------------------------------------------------------------------
__global__ void scan_kernel()
{
    int idx = blockIdx.x * blockDim.x + threadIdx.x;
    if (idx >= Bz * Hz) return;
    int b = idx >> 9;
    int h = idx & (Hz - 1);
    float c = 0.f;
    for (int t = 0; t < Tz; t++) {
        const float* g = g_gates + (size_t)(t * Bz + b) * GATES;
        float gi = g[h];
        float gf = g[h + Hz];
        float gg = g[h + 2 * Hz];
        float go = g[h + 3 * Hz];
        float si = 1.f / (1.f + expf(-gi));
        float sf = 1.f / (1.f + expf(-gf));
        float so = 1.f / (1.f + expf(-go));
        c = sf * c + si * tanhf(gg);
        g_hs[(size_t)(t * Bz + b) * Hz + h] = so * tanhf(c);
    }
}

// ---------------------------------------------------------------------------
// SIMT GEMM for the two small GEMMs (MODE 0: gates, MODE 1: hid)
// ---------------------------------------------------------------------------
#define BM 128
#define BN 128
#define BKq 8
#define TM 8
#define TN 8

template <int MODE>
__global__ void __launch_bounds__(256)
gemm_nt_kernel(const float* __restrict__ Bm,
               const float* __restrict__ bias,
               int M, int N, int K)
{
    __shared__ float As[BKq][BM];
    __shared__ float Bs[BKq][BN];

    const float* A = (MODE == 0) ? g_xseq : g_hs;

    int block_m = blockIdx.y * BM;
    int block_n = blockIdx.x * BN;
    int tid = threadIdx.x;

    int lr = tid >> 1;
    int lk = (tid & 1) * 4;

    const float* Aptr = A + (size_t)(block_m + lr) * K + lk;
    const float* Bptr = Bm + (size_t)(block_n + lr) * K + lk;

    float acc[TM][TN];
    #pragma unroll
    for (int i = 0; i < TM; i++)
        #pragma unroll
        for (int j = 0; j < TN; j++) acc[i][j] = 0.f;

    int tx = tid & 15;
    int ty = tid >> 4;

    for (int k0 = 0; k0 < K; k0 += BKq) {
        float4 av = *(const float4*)Aptr;
        float4 bv = *(const float4*)Bptr;
        __syncthreads();
        As[lk + 0][lr] = av.x; As[lk + 1][lr] = av.y;
        As[lk + 2][lr] = av.z; As[lk + 3][lr] = av.w;
        Bs[lk + 0][lr] = bv.x; Bs[lk + 1][lr] = bv.y;
        Bs[lk + 2][lr] = bv.z; Bs[lk + 3][lr] = bv.w;
        __syncthreads();

        #pragma unroll
        for (int kk = 0; kk < BKq; kk++) {
            float a[TM], b[TN];
            const float4* ap = (const float4*)&As[kk][ty * TM];
            const float4* bp = (const float4*)&Bs[kk][tx * TN];
            float4 a0 = ap[0], a1 = ap[1];
            float4 b0 = bp[0], b1v = bp[1];
            a[0]=a0.x; a[1]=a0.y; a[2]=a0.z; a[3]=a0.w;
            a[4]=a1.x; a[5]=a1.y; a[6]=a1.z; a[7]=a1.w;
            b[0]=b0.x; b[1]=b0.y; b[2]=b0.z; b[3]=b0.w;
            b[4]=b1v.x; b[5]=b1v.y; b[6]=b1v.z; b[7]=b1v.w;
            #pragma unroll
            for (int i = 0; i < TM; i++)
                #pragma unroll
                for (int j = 0; j < TN; j++)
                    acc[i][j] += a[i] * b[j];
        }
        Aptr += BKq;
        Bptr += BKq;
    }

    int n0 = block_n + tx * TN;
    #pragma unroll
    for (int i = 0; i < TM; i++) {
        int m = block_m + ty * TM + i;
        float v[TN];
        #pragma unroll
        for (int j = 0; j < TN; j++) {
            float x = acc[i][j];
            int n = n0 + j;
            if (MODE == 0) x += g_hgates[(size_t)(m & (Bz - 1)) * GATES + n];
            else           x += bias[n];
            v[j] = x;
        }
        float* dst = (MODE == 0) ? (g_gates + (size_t)m * GATES + n0)
                                 : (g_hid + (size_t)m * K2 + n0);
        ((float4*)dst)[0] = make_float4(v[0], v[1], v[2], v[3]);
        ((float4*)dst)[1] = make_float4(v[4], v[5], v[6], v[7]);
    }
}

// ---------------------------------------------------------------------------
// fp32 -> bf16 hi/lo split conversions
// ---------------------------------------------------------------------------
__global__ void convert_w2_kernel(const float* __restrict__ W2)
{
    size_t i = (size_t)blockIdx.x * blockDim.x + threadIdx.x;  // float4 idx
    float4 x = ((const float4*)W2)[i];
    __nv_bfloat16 h0 = __float2bfloat16_rn(x.x);
    __nv_bfloat16 h1 = __float2bfloat16_rn(x.y);
    __nv_bfloat16 h2 = __float2bfloat16_rn(x.z);
    __nv_bfloat16 h3 = __float2bfloat16_rn(x.w);
    __nv_bfloat16 l0 = __float2bfloat16_rn(x.x - __bfloat162float(h0));
    __nv_bfloat16 l1 = __float2bfloat16_rn(x.y - __bfloat162float(h1));
    __nv_bfloat16 l2 = __float2bfloat16_rn(x.z - __bfloat162float(h2));
    __nv_bfloat16 l3 = __float2bfloat16_rn(x.w - __bfloat162float(h3));
    __nv_bfloat162* dh = (__nv_bfloat162*)g_w2hi;
    __nv_bfloat162* dl = (__nv_bfloat162*)g_w2lo;
    dh[i * 2 + 0] = __halves2bfloat162(h0, h1);
    dh[i * 2 + 1] = __halves2bfloat162(h2, h3);
    dl[i * 2 + 0] = __halves2bfloat162(l0, l1);
    dl[i * 2 + 1] = __halves2bfloat162(l2, l3);
}

__global__ void convert_hid_kernel()
{
    size_t i = (size_t)blockIdx.x * blockDim.x + threadIdx.x;  // float4 idx
    float4 x = ((const float4*)g_hid)[i];
    __nv_bfloat16 h0 = __float2bfloat16_rn(x.x);
    __nv_bfloat16 h1 = __float2bfloat16_rn(x.y);
    __nv_bfloat16 h2 = __float2bfloat16_rn(x.z);
    __nv_bfloat16 h3 = __float2bfloat16_rn(x.w);
    __nv_bfloat16 l0 = __float2bfloat16_rn(x.x - __bfloat162float(h0));
    __nv_bfloat16 l1 = __float2bfloat16_rn(x.y - __bfloat162float(h1));
    __nv_bfloat16 l2 = __float2bfloat16_rn(x.z - __bfloat162float(h2));
    __nv_bfloat16 l3 = __float2bfloat16_rn(x.w - __bfloat162float(h3));
    __nv_bfloat162* dh = (__nv_bfloat162*)g_hidhi;
    __nv_bfloat162* dl = (__nv_bfloat162*)g_hidlo;
    dh[i * 2 + 0] = __halves2bfloat162(h0, h1);
    dh[i * 2 + 1] = __halves2bfloat162(h2, h3);
    dl[i * 2 + 0] = __halves2bfloat162(l0, l1);
    dl[i * 2 + 1] = __halves2bfloat162(l2, l3);
}

// ---------------------------------------------------------------------------
// HMMA (mma.sync) logits GEMM: out[b][t][v] = hid @ W2^T + b2
// 3-pass bf16 split into fp32 register accumulators.
// CTA tile 128(m) x 128(n), KC=32 double-buffered via cp.async.
// 8 warps in a 4(m) x 2(n) grid -> warp tile 32 x 64.
// SMEM rows padded to 40 bf16 (80B) -> conflict-free ldmatrix.
// Grid: x = 16 m-tiles (fast dim -> consecutive CTAs share the B tile in L2),
//       y = 393 n-tiles.
// ---------------------------------------------------------------------------
#define KC 32
#define AROW 40                         // KC + 8 pad, in bf16 elems (80 bytes)
#define ATILE_B (128 * AROW * 2)        // 10240 bytes per 128x32 tile
#define STAGE_B (4 * ATILE_B)           // Ahi, Alo, Bhi, Blo
#define LOGITS_SMEM (2 * STAGE_B)       // 81920

__global__ void __launch_bounds__(256, 1)
logits_mma_kernel(const float* __restrict__ b2, float* __restrict__ out)
{
    extern __shared__ char dynsmem[];
    uint32_t smem = smem_u32(dynsmem);

    int tid  = threadIdx.x;
    int wid  = tid >> 5;
    int lane = tid & 31;
    int wm   = wid & 3;                 // warp m index (32 rows each)
    int wn   = wid >> 2;                // warp n index (64 cols each)

    int m0 = blockIdx.x * 128;
    int n0 = blockIdx.y * 128;

    // global load assignment: thread -> (row r, 32B half h)
    int r = tid >> 1;
    int h = tid & 1;
    const char* ah_row = (const char*)(g_hidhi + (size_t)(m0 + r) * K2);
    const char* al_row = (const char*)(g_hidlo + (size_t)(m0 + r) * K2);
    int  brow = n0 + r;
    if (brow >= Vz) brow = 0;           // clamp: finite garbage, masked at store
    const char* bh_row = (const char*)(g_w2hi + (size_t)brow * K2);
    const char* bl_row = (const char*)(g_w2lo + (size_t)brow * K2);
    uint32_t sdst = (uint32_t)r * 80u + (uint32_t)h * 32u;

    float acc[2][8][4];
    #pragma unroll
    for (int i = 0; i < 2; i++)
        #pragma unroll
        for (int j = 0; j < 8; j++)
            #pragma unroll
            for (int q = 0; q < 4; q++) acc[i][j][q] = 0.f;

    // ldmatrix lane-derived offsets
    int a_lrow  = lane & 15;            // row within 16
    int a_lcol  = (lane >> 4) << 3;     // 0 or 8 (k elems)
    int b_mid   = lane >> 3;            // matrix index 0..3
    int b_lrow  = lane & 7;
    int b_pair  = b_mid >> 1;           // 0/1: which n-frag of the pair
    int b_half  = b_mid & 1;            // 0/1: k 0-7 vs 8-15 (16B)

    // issue loads for one stage
    auto load_stage = [&](int s, int kc) {
        uint32_t st = smem + (uint32_t)s * STAGE_B;
        int koff = kc * KC * 2;         // byte offset in bf16 row
        int go = koff + h * 32;
        uint32_t d = st + sdst;
        CP16(d,                  ah_row + go);
        CP16(d + 16,             ah_row + go + 16);
        CP16(d + ATILE_B,        al_row + go);
        CP16(d + ATILE_B + 16,   al_row + go + 16);
        CP16(d + 2 * ATILE_B,      bh_row + go);
        CP16(d + 2 * ATILE_B + 16, bh_row + go + 16);
        CP16(d + 3 * ATILE_B,      bl_row + go);
        CP16(d + 3 * ATILE_B + 16, bl_row + go + 16);
    };

    const int NKC = K2 / KC;            // 32
    load_stage(0, 0);
    CP_COMMIT();

    for (int kc = 0; kc < NKC; kc++) {
        int cur = kc & 1;
        if (kc + 1 < NKC) {
            load_stage(cur ^ 1, kc + 1);
            CP_COMMIT();
            CP_WAIT(1);
        } else {
            CP_WAIT(0);
        }
        __syncthreads();

        uint32_t st = smem + (uint32_t)cur * STAGE_B;
        #pragma unroll
        for (int ks = 0; ks < 2; ks++) {
            uint32_t ahf[2][4], alf[2][4];
            #pragma unroll
            for (int im = 0; im < 2; im++) {
                uint32_t aaddr = st
                    + (uint32_t)(wm * 32 + im * 16 + a_lrow) * 80u
                    + (uint32_t)(ks * 16 + a_lcol) * 2u;
                ldsm4(ahf[im], aaddr);
                ldsm4(alf[im], aaddr + ATILE_B);
            }
            #pragma unroll
            for (int jp = 0; jp < 4; jp++) {
                uint32_t baddr = st + 2 * ATILE_B
                    + (uint32_t)(wn * 64 + (jp * 2 + b_pair) * 8 + b_lrow) * 80u
                    + (uint32_t)(ks * 32 + b_half * 16);
                uint32_t bhf[4], blf[4];
                ldsm4(bhf, baddr);
                ldsm4(blf, baddr + ATILE_B);
                #pragma unroll
                for (int im = 0; im < 2; im++) {
                    mma16816(acc[im][jp * 2 + 0], ahf[im], bhf + 0);
                    mma16816(acc[im][jp * 2 + 1], ahf[im], bhf + 2);
                    mma16816(acc[im][jp * 2 + 0], alf[im], bhf + 0);
                    mma16816(acc[im][jp * 2 + 1], alf[im], bhf + 2);
                    mma16816(acc[im][jp * 2 + 0], ahf[im], blf + 0);
                    mma16816(acc[im][jp * 2 + 1], ahf[im], blf + 2);
                }
            }
        }
        __syncthreads();                // before overwriting buffer `cur`
    }

    // Epilogue: acc -> out[(b)(t)][v] + b2. Scalar stores (Vz odd).
    int grp = lane >> 2;                // 0..7
    int qid = lane & 3;                 // 0..3
    #pragma unroll
    for (int im = 0; im < 2; im++) {
        int mrow0 = m0 + wm * 32 + im * 16 + grp;
        #pragma unroll
        for (int half = 0; half < 2; half++) {
            int mrow = mrow0 + half * 8;
            int bb = mrow & 31;
            int tt = mrow >> 5;
            float* orow = out + ((size_t)bb * Tz + tt) * Vz;
            #pragma unroll
            for (int jn = 0; jn < 8; jn++) {
                int col = n0 + wn * 64 + jn * 8 + qid * 2;
                if (col < Vz) {
                    float bias0 = b2[col];
                    orow[col] = acc[im][jn][half * 2 + 0] + bias0;
                    if (col + 1 < Vz)
                        orow[col + 1] = acc[im][jn][half * 2 + 1] + b2[col + 1];
                }
            }
        }
    }
}

// ---------------------------------------------------------------------------
// Launch
// ---------------------------------------------------------------------------
extern "C" void kernel_launch(void* const* d_in, const int* in_sizes, int n_in,
                              void* d_out, int out_size)
{
    const float* features = (const float*)d_in[0];
    const int*   captions = (const int*)d_in[1];
    const float* emb      = (const float*)d_in[2];
    const float* W_ih     = (const float*)d_in[3];
    const float* W_hh     = (const float*)d_in[4];
    const float* b_ih     = (const float*)d_in[5];
    const float* b_hh     = (const float*)d_in[6];
    const float* W1       = (const float*)d_in[7];
    const float* b1       = (const float*)d_in[8];
    const float* W2       = (const float*)d_in[9];
    const float* b2       = (const float*)d_in[10];
    float* out = (float*)d_out;

    cudaFuncSetAttribute(logits_mma_kernel,
                         cudaFuncAttributeMaxDynamicSharedMemorySize, LOGITS_SMEM);

    // W2 split conversion (independent; overlaps the front-end)
    convert_w2_kernel<<<(int)(((size_t)Vz * K2 / 4) / 256), 256>>>(W2);

    // 1) gather shifted embeddings
    gather_kernel<<<Mz, Ez / 4>>>(captions, emb);

    // 2) h_gates (+ both biases)
    hgates_kernel<<<(Bz * GATES + 255) / 256, 256>>>(features, W_hh, b_ih, b_hh);

    // 3) gates GEMM (2048 x 2048 x 256) + h_gates
    {
        dim3 grid(GATES / BN, Mz / BM);
        gemm_nt_kernel<0><<<grid, 256>>>(W_ih, nullptr, Mz, GATES, Ez);
    }

    // 4) LSTM scan
    scan_kernel<<<(Bz * Hz + 255) / 256, 256>>>();

    // 5) hid GEMM (2048 x 1024 x 512) + b1
    {
        dim3 grid(K2 / BN, Mz / BM);
        gemm_nt_kernel<1><<<grid, 256>>>(W1, b1, Mz, K2, Hz);
    }

    // 6) hid -> bf16 hi/lo
    convert_hid_kernel<<<(int)(((size_t)Mz * K2 / 4) / 256), 256>>>();

    // 7) HMMA logits GEMM (2048 x 50257 x 1024) + b2
    {
        dim3 grid(Mz / 128, (Vz + 127) / 128);  // (16, 393)
        logits_mma_kernel<<<grid, 256, LOGITS_SMEM>>>(b2, out);
    }
}

// round 6
// speedup vs baseline: 2.1502x; 1.0362x over previous
#include <cuda_runtime.h>
#include <cuda_bf16.h>
#include <math.h>
#include <stdint.h>

// Problem constants
#define Bz 32
#define Tz 64
#define Vz 50257
#define Ez 256
#define Hz 512
#define GATES 2048          // 4*H
#define Mz 2048             // T*B
#define K2 1024             // 2*H

// ---------------------------------------------------------------------------
// Scratch (static device allocations only)
// ---------------------------------------------------------------------------
__device__ float g_xseq[Mz * Ez];
__device__ float g_hgates[Bz * GATES];
__device__ float g_gates[(size_t)Mz * GATES];
__device__ float g_hs[(size_t)Mz * Hz];
__device__ float g_hid[(size_t)Mz * K2];

// bf16 split operands for the tensor-core logits GEMM
__device__ __nv_bfloat16 g_w2hi[(size_t)Vz * K2];   // ~103 MB
__device__ __nv_bfloat16 g_w2lo[(size_t)Vz * K2];   // ~103 MB
__device__ __nv_bfloat16 g_hidhi[(size_t)Mz * K2];  // 4 MB
__device__ __nv_bfloat16 g_hidlo[(size_t)Mz * K2];  // 4 MB

// ---------------------------------------------------------------------------
// PTX helpers (base PTX only — NO tcgen05; harness assembles for sm_103 base)
// ---------------------------------------------------------------------------
__device__ __forceinline__ uint32_t smem_u32(const void* p) {
    uint32_t a;
    asm("{ .reg .u64 t; cvta.to.shared.u64 t, %1; cvt.u32.u64 %0, t; }"
        : "=r"(a) : "l"(p));
    return a;
}
#define CP16(dst, src) \
    asm volatile("cp.async.cg.shared.global [%0], [%1], 16;" :: "r"(dst), "l"(src) : "memory")
#define CP_COMMIT()  asm volatile("cp.async.commit_group;" ::: "memory")
#define CP_WAIT(n)   asm volatile("cp.async.wait_group %0;" :: "n"(n) : "memory")

__device__ __forceinline__ void ldsm4(uint32_t* r, uint32_t addr) {
    asm volatile("ldmatrix.sync.aligned.m8n8.x4.shared.b16 {%0,%1,%2,%3}, [%4];"
                 : "=r"(r[0]), "=r"(r[1]), "=r"(r[2]), "=r"(r[3]) : "r"(addr));
}
__device__ __forceinline__ void mma16816(float* c, const uint32_t* a, const uint32_t* b) {
    asm volatile("mma.sync.aligned.m16n8k16.row.col.f32.bf16.bf16.f32 "
                 "{%0,%1,%2,%3}, {%4,%5,%6,%7}, {%8,%9}, {%0,%1,%2,%3};"
                 : "+f"(c[0]), "+f"(c[1]), "+f"(c[2]), "+f"(c[3])
                 : "r"(a[0]), "r"(a[1]), "r"(a[2]), "r"(a[3]),
                   "r"(b[0]), "r"(b[1]));
}

// ---------------------------------------------------------------------------
// Kernel 1: gather shifted caption embeddings.
// ---------------------------------------------------------------------------
__global__ void gather_kernel(const int* __restrict__ captions,
                              const float* __restrict__ emb)
{
    int m = blockIdx.x;
    int t = m / Bz;
    int b = m % Bz;
    int src_t = (t == 0) ? 0 : (t - 1);
    int token = captions[b * Tz + src_t];
    const float4* src = (const float4*)(emb + (size_t)token * Ez);
    float4* dst = (float4*)(g_xseq + (size_t)m * Ez);
    dst[threadIdx.x] = src[threadIdx.x];
}

// ---------------------------------------------------------------------------
// Kernel 2: h_gates
// ---------------------------------------------------------------------------
__global__ void hgates_kernel(const float* __restrict__ features,
                              const float* __restrict__ W_hh,
                              const float* __restrict__ b_ih,
                              const float* __restrict__ b_hh)
{
    int idx = blockIdx.x * blockDim.x + threadIdx.x;
    if (idx >= Bz * GATES) return;
    int b = idx / GATES;
    int g = idx % GATES;
    const float4* w = (const float4*)(W_hh + (size_t)g * Hz);
    const float4* f = (const float4*)(features + (size_t)b * Hz);
    float s = b_ih[g] + b_hh[g];
    #pragma unroll 4
    for (int k = 0; k < Hz / 4; k++) {
        float4 wv = w[k];
        float4 fv = f[k];
        s += fv.x * wv.x + fv.y * wv.y + fv.z * wv.z + fv.w * wv.w;
    }
    g_hgates[idx] = s;
}

// ---------------------------------------------------------------------------
// Kernel 3: elementwise LSTM scan, software-pipelined (prefetch t+1 gates).
// ---------------------------------------------------------------------------
__global__ void scan_kernel()
{
    int idx = blockIdx.x * blockDim.x + threadIdx.x;
    if (idx >= Bz * Hz) return;
    int b = idx >> 9;
    int h = idx & (Hz - 1);
    float c = 0.f;

    const float* g0 = g_gates + (size_t)b * GATES;   // t = 0 row
    float ni = g0[h];
    float nf = g0[h + Hz];
    float ng = g0[h + 2 * Hz];
    float no = g0[h + 3 * Hz];

    for (int t = 0; t < Tz; t++) {
        float gi = ni, gf = nf, gg = ng, go = no;
        if (t + 1 < Tz) {
            const float* gn = g_gates + (size_t)((t + 1) * Bz + b) * GATES;
            ni = gn[h];
            nf = gn[h + Hz];
            ng = gn[h + 2 * Hz];
            no = gn[h + 3 * Hz];
        }
        float si = 1.f / (1.f + expf(-gi));
        float sf = 1.f / (1.f + expf(-gf));
        float so = 1.f / (1.f + expf(-go));
        c = sf * c + si * tanhf(gg);
        g_hs[(size_t)(t * Bz + b) * Hz + h] = so * tanhf(c);
    }
}

// ---------------------------------------------------------------------------
// SIMT GEMM for the two small GEMMs (MODE 0: gates, MODE 1: hid)
// ---------------------------------------------------------------------------
#define BM 128
#define BN 128
#define BKq 8
#define TM 8
#define TN 8

template <int MODE>
__global__ void __launch_bounds__(256)
gemm_nt_kernel(const float* __restrict__ Bm,
               const float* __restrict__ bias,
               int M, int N, int K)
{
    __shared__ float As[BKq][BM];
    __shared__ float Bs[BKq][BN];

    const float* A = (MODE == 0) ? g_xseq : g_hs;

    int block_m = blockIdx.y * BM;
    int block_n = blockIdx.x * BN;
    int tid = threadIdx.x;

    int lr = tid >> 1;
    int lk = (tid & 1) * 4;

    const float* Aptr = A + (size_t)(block_m + lr) * K + lk;
    const float* Bptr = Bm + (size_t)(block_n + lr) * K + lk;

    float acc[TM][TN];
    #pragma unroll
    for (int i = 0; i < TM; i++)
        #pragma unroll
        for (int j = 0; j < TN; j++) acc[i][j] = 0.f;

    int tx = tid & 15;
    int ty = tid >> 4;

    for (int k0 = 0; k0 < K; k0 += BKq) {
        float4 av = *(const float4*)Aptr;
        float4 bv = *(const float4*)Bptr;
        __syncthreads();
        As[lk + 0][lr] = av.x; As[lk + 1][lr] = av.y;
        As[lk + 2][lr] = av.z; As[lk + 3][lr] = av.w;
        Bs[lk + 0][lr] = bv.x; Bs[lk + 1][lr] = bv.y;
        Bs[lk + 2][lr] = bv.z; Bs[lk + 3][lr] = bv.w;
        __syncthreads();

        #pragma unroll
        for (int kk = 0; kk < BKq; kk++) {
            float a[TM], b[TN];
            const float4* ap = (const float4*)&As[kk][ty * TM];
            const float4* bp = (const float4*)&Bs[kk][tx * TN];
            float4 a0 = ap[0], a1 = ap[1];
            float4 b0 = bp[0], b1v = bp[1];
            a[0]=a0.x; a[1]=a0.y; a[2]=a0.z; a[3]=a0.w;
            a[4]=a1.x; a[5]=a1.y; a[6]=a1.z; a[7]=a1.w;
            b[0]=b0.x; b[1]=b0.y; b[2]=b0.z; b[3]=b0.w;
            b[4]=b1v.x; b[5]=b1v.y; b[6]=b1v.z; b[7]=b1v.w;
            #pragma unroll
            for (int i = 0; i < TM; i++)
                #pragma unroll
                for (int j = 0; j < TN; j++)
                    acc[i][j] += a[i] * b[j];
        }
        Aptr += BKq;
        Bptr += BKq;
    }

    int n0 = block_n + tx * TN;
    #pragma unroll
    for (int i = 0; i < TM; i++) {
        int m = block_m + ty * TM + i;
        float v[TN];
        #pragma unroll
        for (int j = 0; j < TN; j++) {
            float x = acc[i][j];
            int n = n0 + j;
            if (MODE == 0) x += g_hgates[(size_t)(m & (Bz - 1)) * GATES + n];
            else           x += bias[n];
            v[j] = x;
        }
        float* dst = (MODE == 0) ? (g_gates + (size_t)m * GATES + n0)
                                 : (g_hid + (size_t)m * K2 + n0);
        ((float4*)dst)[0] = make_float4(v[0], v[1], v[2], v[3]);
        ((float4*)dst)[1] = make_float4(v[4], v[5], v[6], v[7]);
    }
}

// ---------------------------------------------------------------------------
// fp32 -> bf16 hi/lo split conversions
// ---------------------------------------------------------------------------
__global__ void convert_w2_kernel(const float* __restrict__ W2)
{
    size_t i = (size_t)blockIdx.x * blockDim.x + threadIdx.x;  // float4 idx
    float4 x = ((const float4*)W2)[i];
    __nv_bfloat16 h0 = __float2bfloat16_rn(x.x);
    __nv_bfloat16 h1 = __float2bfloat16_rn(x.y);
    __nv_bfloat16 h2 = __float2bfloat16_rn(x.z);
    __nv_bfloat16 h3 = __float2bfloat16_rn(x.w);
    __nv_bfloat16 l0 = __float2bfloat16_rn(x.x - __bfloat162float(h0));
    __nv_bfloat16 l1 = __float2bfloat16_rn(x.y - __bfloat162float(h1));
    __nv_bfloat16 l2 = __float2bfloat16_rn(x.z - __bfloat162float(h2));
    __nv_bfloat16 l3 = __float2bfloat16_rn(x.w - __bfloat162float(h3));
    __nv_bfloat162* dh = (__nv_bfloat162*)g_w2hi;
    __nv_bfloat162* dl = (__nv_bfloat162*)g_w2lo;
    dh[i * 2 + 0] = __halves2bfloat162(h0, h1);
    dh[i * 2 + 1] = __halves2bfloat162(h2, h3);
    dl[i * 2 + 0] = __halves2bfloat162(l0, l1);
    dl[i * 2 + 1] = __halves2bfloat162(l2, l3);
}

__global__ void convert_hid_kernel()
{
    size_t i = (size_t)blockIdx.x * blockDim.x + threadIdx.x;  // float4 idx
    float4 x = ((const float4*)g_hid)[i];
    __nv_bfloat16 h0 = __float2bfloat16_rn(x.x);
    __nv_bfloat16 h1 = __float2bfloat16_rn(x.y);
    __nv_bfloat16 h2 = __float2bfloat16_rn(x.z);
    __nv_bfloat16 h3 = __float2bfloat16_rn(x.w);
    __nv_bfloat16 l0 = __float2bfloat16_rn(x.x - __bfloat162float(h0));
    __nv_bfloat16 l1 = __float2bfloat16_rn(x.y - __bfloat162float(h1));
    __nv_bfloat16 l2 = __float2bfloat16_rn(x.z - __bfloat162float(h2));
    __nv_bfloat16 l3 = __float2bfloat16_rn(x.w - __bfloat162float(h3));
    __nv_bfloat162* dh = (__nv_bfloat162*)g_hidhi;
    __nv_bfloat162* dl = (__nv_bfloat162*)g_hidlo;
    dh[i * 2 + 0] = __halves2bfloat162(h0, h1);
    dh[i * 2 + 1] = __halves2bfloat162(h2, h3);
    dl[i * 2 + 0] = __halves2bfloat162(l0, l1);
    dl[i * 2 + 1] = __halves2bfloat162(l2, l3);
}

// ---------------------------------------------------------------------------
// HMMA logits GEMM: out[b][t][v] = hid @ W2^T + b2, 3-pass bf16 split.
// CTA tile 128(m) x 256(n), KC=32, 3-stage cp.async pipeline, one sync/chunk.
// 8 warps in 2(m) x 4(n) grid -> 64x64 warp tiles (mma:ldsm = 6:1).
// SMEM rows padded to 40 bf16 (80B) -> conflict-free ldmatrix.
// ---------------------------------------------------------------------------
#define KC 32
#define NROW 40                          // KC + 8 pad, bf16 elems (80 bytes)
#define A_T (128 * NROW * 2)             // 10240 B: one 128x32 tile
#define B_T (256 * NROW * 2)             // 20480 B: one 256x32 tile
#define STAGE (2 * A_T + 2 * B_T)        // 61440 B: Ahi, Alo, Bhi, Blo
#define NSTAGE 3
#define LOGITS_SMEM (NSTAGE * STAGE)     // 184320 B

__global__ void __launch_bounds__(256, 1)
logits_mma_kernel(const float* __restrict__ b2, float* __restrict__ out)
{
    extern __shared__ char dynsmem[];
    uint32_t smem = smem_u32(dynsmem);

    int tid  = threadIdx.x;
    int wid  = tid >> 5;
    int lane = tid & 31;
    int wm   = wid & 1;                  // warp m index (64 rows)
    int wn   = wid >> 1;                 // warp n index (64 cols)

    int m0 = blockIdx.x * 128;
    int n0 = blockIdx.y * 256;

    // global->smem load assignment
    int ra = tid >> 1;                   // A row 0..127 (2 threads/row)
    int hh = tid & 1;                    // 32B half
    const char* ah_row = (const char*)(g_hidhi + (size_t)(m0 + ra) * K2);
    const char* al_row = (const char*)(g_hidlo + (size_t)(m0 + ra) * K2);
    int brow = n0 + tid;                 // B row 0..255 (1 thread/row)
    if (brow >= Vz) brow = 0;            // clamp: finite garbage, masked at store
    const char* bh_row = (const char*)(g_w2hi + (size_t)brow * K2);
    const char* bl_row = (const char*)(g_w2lo + (size_t)brow * K2);
    uint32_t a_dst = (uint32_t)ra * 80u + (uint32_t)hh * 32u;
    uint32_t b_dst = (uint32_t)tid * 80u;

    float acc[4][8][4];
    #pragma unroll
    for (int i = 0; i < 4; i++)
        #pragma unroll
        for (int j = 0; j < 8; j++)
            #pragma unroll
            for (int q = 0; q < 4; q++) acc[i][j][q] = 0.f;

    // ldmatrix lane-derived offsets
    int a_lrow = lane & 15;
    int a_koff = (lane >> 4) * 16;       // bytes
    int b_mid  = lane >> 3;
    int b_lrow = lane & 7;
    int b_pair = b_mid >> 1;
    int b_half = b_mid & 1;

    auto load_stage = [&](int s, int kc) {
        uint32_t st = smem + (uint32_t)s * STAGE;
        int go = kc * (KC * 2);          // byte offset into bf16 row
        // A hi/lo: 2 x 16B per tensor per thread
        CP16(st + a_dst,            ah_row + go + hh * 32);
        CP16(st + a_dst + 16,       ah_row + go + hh * 32 + 16);
        CP16(st + A_T + a_dst,      al_row + go + hh * 32);
        CP16(st + A_T + a_dst + 16, al_row + go + hh * 32 + 16);
        // B hi/lo: 4 x 16B per tensor per thread
        uint32_t bb = st + 2 * A_T + b_dst;
        #pragma unroll
        for (int j = 0; j < 4; j++) {
            CP16(bb + j * 16,        bh_row + go + j * 16);
            CP16(bb + B_T + j * 16,  bl_row + go + j * 16);
        }
        CP_COMMIT();
    };

    const int NKC = K2 / KC;             // 32
    load_stage(0, 0);
    load_stage(1, 1);

    for (int kc = 0; kc < NKC; kc++) {
        CP_WAIT(1);                      // group kc arrived
        __syncthreads();                 // data visible; buffer (kc+2)%3 free
        if (kc + 2 < NKC) load_stage((kc + 2) % 3, kc + 2);

        uint32_t st = smem + (uint32_t)(kc % 3) * STAGE;
        #pragma unroll
        for (int ks = 0; ks < 2; ks++) {
            uint32_t ahf[4][4], alf[4][4];
            #pragma unroll
            for (int im = 0; im < 4; im++) {
                uint32_t aaddr = st
                    + (uint32_t)(wm * 64 + im * 16 + a_lrow) * 80u
                    + (uint32_t)(ks * 32 + a_koff);
                ldsm4(ahf[im], aaddr);
                ldsm4(alf[im], aaddr + A_T);
            }
            #pragma unroll
            for (int jp = 0; jp < 4; jp++) {
                uint32_t baddr = st + 2 * A_T
                    + (uint32_t)(wn * 64 + (jp * 2 + b_pair) * 8 + b_lrow) * 80u
                    + (uint32_t)(ks * 32 + b_half * 16);
                uint32_t bhf[4], blf[4];
                ldsm4(bhf, baddr);
                ldsm4(blf, baddr + B_T);
                #pragma unroll
                for (int im = 0; im < 4; im++) {
                    mma16816(acc[im][jp * 2 + 0], ahf[im], bhf + 0);
                    mma16816(acc[im][jp * 2 + 1], ahf[im], bhf + 2);
                    mma16816(acc[im][jp * 2 + 0], alf[im], bhf + 0);
                    mma16816(acc[im][jp * 2 + 1], alf[im], bhf + 2);
                    mma16816(acc[im][jp * 2 + 0], ahf[im], blf + 0);
                    mma16816(acc[im][jp * 2 + 1], ahf[im], blf + 2);
                }
            }
        }
        // no trailing sync: buffer (kc%3) is only rewritten at iter kc+1,
        // after that iteration's __syncthreads.
    }

    // Epilogue: acc -> out[(b)(t)][v] + b2. Scalar stores (Vz odd).
    int grp = lane >> 2;
    int qid = lane & 3;
    #pragma unroll
    for (int im = 0; im < 4; im++) {
        #pragma unroll
        for (int half = 0; half < 2; half++) {
            int mrow = m0 + wm * 64 + im * 16 + grp + half * 8;
            int bb = mrow & 31;
            int tt = mrow >> 5;
            float* orow = out + ((size_t)bb * Tz + tt) * Vz;
            #pragma unroll
            for (int jf = 0; jf < 8; jf++) {
                int col = n0 + wn * 64 + (jf >> 1) * 16 + (jf & 1) * 8 + qid * 2;
                if (col < Vz) {
                    orow[col] = acc[im][jf][half * 2 + 0] + b2[col];
                    if (col + 1 < Vz)
                        orow[col + 1] = acc[im][jf][half * 2 + 1] + b2[col + 1];
                }
            }
        }
    }
}

// ---------------------------------------------------------------------------
// Launch
// ---------------------------------------------------------------------------
extern "C" void kernel_launch(void* const* d_in, const int* in_sizes, int n_in,
                              void* d_out, int out_size)
{
    const float* features = (const float*)d_in[0];
    const int*   captions = (const int*)d_in[1];
    const float* emb      = (const float*)d_in[2];
    const float* W_ih     = (const float*)d_in[3];
    const float* W_hh     = (const float*)d_in[4];
    const float* b_ih     = (const float*)d_in[5];
    const float* b_hh     = (const float*)d_in[6];
    const float* W1       = (const float*)d_in[7];
    const float* b1       = (const float*)d_in[8];
    const float* W2       = (const float*)d_in[9];
    const float* b2       = (const float*)d_in[10];
    float* out = (float*)d_out;

    cudaFuncSetAttribute(logits_mma_kernel,
                         cudaFuncAttributeMaxDynamicSharedMemorySize, LOGITS_SMEM);

    // W2 split conversion (independent; overlaps the front-end)
    convert_w2_kernel<<<(int)(((size_t)Vz * K2 / 4) / 256), 256>>>(W2);

    // 1) gather shifted embeddings
    gather_kernel<<<Mz, Ez / 4>>>(captions, emb);

    // 2) h_gates (+ both biases)
    hgates_kernel<<<(Bz * GATES + 255) / 256, 256>>>(features, W_hh, b_ih, b_hh);

    // 3) gates GEMM (2048 x 2048 x 256) + h_gates
    {
        dim3 grid(GATES / BN, Mz / BM);
        gemm_nt_kernel<0><<<grid, 256>>>(W_ih, nullptr, Mz, GATES, Ez);
    }

    // 4) LSTM scan
    scan_kernel<<<(Bz * Hz + 255) / 256, 256>>>();

    // 5) hid GEMM (2048 x 1024 x 512) + b1
    {
        dim3 grid(K2 / BN, Mz / BM);
        gemm_nt_kernel<1><<<grid, 256>>>(W1, b1, Mz, K2, Hz);
    }

    // 6) hid -> bf16 hi/lo
    convert_hid_kernel<<<(int)(((size_t)Mz * K2 / 4) / 256), 256>>>();

    // 7) HMMA logits GEMM (2048 x 50257 x 1024) + b2
    {
        dim3 grid(Mz / 128, (Vz + 255) / 256);  // (16, 197)
        logits_mma_kernel<<<grid, 256, LOGITS_SMEM>>>(b2, out);
    }
}

// round 7
// speedup vs baseline: 2.9137x; 1.3551x over previous
#include <cuda_runtime.h>
#include <cuda_bf16.h>
#include <cuda_fp16.h>
#include <math.h>
#include <stdint.h>

// Problem constants
#define Bz 32
#define Tz 64
#define Vz 50257
#define Ez 256
#define Hz 512
#define GATES 2048          // 4*H
#define Mz 2048             // T*B
#define K2 1024             // 2*H

// ---------------------------------------------------------------------------
// Scratch (static device allocations only)
// ---------------------------------------------------------------------------
__device__ float g_xseq[Mz * Ez];
__device__ float g_hgates[Bz * GATES];
__device__ float g_gates[(size_t)Mz * GATES];
__device__ float g_hs[(size_t)Mz * Hz];
__device__ float g_hid[(size_t)Mz * K2];

// fp16 operands for the 2-pass split logits GEMM
__device__ __half g_w2h[(size_t)Vz * K2];    // ~103 MB, W2 rounded to fp16
__device__ __half g_hidhi[(size_t)Mz * K2];  // 4 MB, hi part of hid
__device__ __half g_hidlo[(size_t)Mz * K2];  // 4 MB, residual of hid

// ---------------------------------------------------------------------------
// PTX helpers (base PTX only — NO tcgen05; harness assembles for sm_103 base)
// ---------------------------------------------------------------------------
__device__ __forceinline__ uint32_t smem_u32(const void* p) {
    uint32_t a;
    asm("{ .reg .u64 t; cvta.to.shared.u64 t, %1; cvt.u32.u64 %0, t; }"
        : "=r"(a) : "l"(p));
    return a;
}
#define CP16(dst, src) \
    asm volatile("cp.async.cg.shared.global [%0], [%1], 16;" :: "r"(dst), "l"(src) : "memory")
#define CP_COMMIT()  asm volatile("cp.async.commit_group;" ::: "memory")
#define CP_WAIT(n)   asm volatile("cp.async.wait_group %0;" :: "n"(n) : "memory")

__device__ __forceinline__ void ldsm4(uint32_t* r, uint32_t addr) {
    asm volatile("ldmatrix.sync.aligned.m8n8.x4.shared.b16 {%0,%1,%2,%3}, [%4];"
                 : "=r"(r[0]), "=r"(r[1]), "=r"(r[2]), "=r"(r[3]) : "r"(addr));
}
__device__ __forceinline__ void mma16816(float* c, const uint32_t* a, const uint32_t* b) {
    asm volatile("mma.sync.aligned.m16n8k16.row.col.f32.f16.f16.f32 "
                 "{%0,%1,%2,%3}, {%4,%5,%6,%7}, {%8,%9}, {%0,%1,%2,%3};"
                 : "+f"(c[0]), "+f"(c[1]), "+f"(c[2]), "+f"(c[3])
                 : "r"(a[0]), "r"(a[1]), "r"(a[2]), "r"(a[3]),
                   "r"(b[0]), "r"(b[1]));
}

// ---------------------------------------------------------------------------
// Kernel 1: gather shifted caption embeddings.
// ---------------------------------------------------------------------------
__global__ void gather_kernel(const int* __restrict__ captions,
                              const float* __restrict__ emb)
{
    int m = blockIdx.x;
    int t = m / Bz;
    int b = m % Bz;
    int src_t = (t == 0) ? 0 : (t - 1);
    int token = captions[b * Tz + src_t];
    const float4* src = (const float4*)(emb + (size_t)token * Ez);
    float4* dst = (float4*)(g_xseq + (size_t)m * Ez);
    dst[threadIdx.x] = src[threadIdx.x];
}

// ---------------------------------------------------------------------------
// Kernel 2: h_gates
// ---------------------------------------------------------------------------
__global__ void hgates_kernel(const float* __restrict__ features,
                              const float* __restrict__ W_hh,
                              const float* __restrict__ b_ih,
                              const float* __restrict__ b_hh)
{
    int idx = blockIdx.x * blockDim.x + threadIdx.x;
    if (idx >= Bz * GATES) return;
    int b = idx / GATES;
    int g = idx % GATES;
    const float4* w = (const float4*)(W_hh + (size_t)g * Hz);
    const float4* f = (const float4*)(features + (size_t)b * Hz);
    float s = b_ih[g] + b_hh[g];
    #pragma unroll 4
    for (int k = 0; k < Hz / 4; k++) {
        float4 wv = w[k];
        float4 fv = f[k];
        s += fv.x * wv.x + fv.y * wv.y + fv.z * wv.z + fv.w * wv.w;
    }
    g_hgates[idx] = s;
}

// ---------------------------------------------------------------------------
// Kernel 3: elementwise LSTM scan, software-pipelined (prefetch t+1 gates).
// ---------------------------------------------------------------------------
__global__ void scan_kernel()
{
    int idx = blockIdx.x * blockDim.x + threadIdx.x;
    if (idx >= Bz * Hz) return;
    int b = idx >> 9;
    int h = idx & (Hz - 1);
    float c = 0.f;

    const float* g0 = g_gates + (size_t)b * GATES;   // t = 0 row
    float ni = g0[h];
    float nf = g0[h + Hz];
    float ng = g0[h + 2 * Hz];
    float no = g0[h + 3 * Hz];

    for (int t = 0; t < Tz; t++) {
        float gi = ni, gf = nf, gg = ng, go = no;
        if (t + 1 < Tz) {
            const float* gn = g_gates + (size_t)((t + 1) * Bz + b) * GATES;
            ni = gn[h];
            nf = gn[h + Hz];
            ng = gn[h + 2 * Hz];
            no = gn[h + 3 * Hz];
        }
        float si = 1.f / (1.f + expf(-gi));
        float sf = 1.f / (1.f + expf(-gf));
        float so = 1.f / (1.f + expf(-go));
        c = sf * c + si * tanhf(gg);
        g_hs[(size_t)(t * Bz + b) * Hz + h] = so * tanhf(c);
    }
}

// ---------------------------------------------------------------------------
// SIMT GEMM for the two small GEMMs (MODE 0: gates, MODE 1: hid)
// ---------------------------------------------------------------------------
#define BM 128
#define BN 128
#define BKq 8
#define TM 8
#define TN 8

template <int MODE>
__global__ void __launch_bounds__(256)
gemm_nt_kernel(const float* __restrict__ Bm,
               const float* __restrict__ bias,
               int M, int N, int K)
{
    __shared__ float As[BKq][BM];
    __shared__ float Bs[BKq][BN];

    const float* A = (MODE == 0) ? g_xseq : g_hs;

    int block_m = blockIdx.y * BM;
    int block_n = blockIdx.x * BN;
    int tid = threadIdx.x;

    int lr = tid >> 1;
    int lk = (tid & 1) * 4;

    const float* Aptr = A + (size_t)(block_m + lr) * K + lk;
    const float* Bptr = Bm + (size_t)(block_n + lr) * K + lk;

    float acc[TM][TN];
    #pragma unroll
    for (int i = 0; i < TM; i++)
        #pragma unroll
        for (int j = 0; j < TN; j++) acc[i][j] = 0.f;

    int tx = tid & 15;
    int ty = tid >> 4;

    for (int k0 = 0; k0 < K; k0 += BKq) {
        float4 av = *(const float4*)Aptr;
        float4 bv = *(const float4*)Bptr;
        __syncthreads();
        As[lk + 0][lr] = av.x; As[lk + 1][lr] = av.y;
        As[lk + 2][lr] = av.z; As[lk + 3][lr] = av.w;
        Bs[lk + 0][lr] = bv.x; Bs[lk + 1][lr] = bv.y;
        Bs[lk + 2][lr] = bv.z; Bs[lk + 3][lr] = bv.w;
        __syncthreads();

        #pragma unroll
        for (int kk = 0; kk < BKq; kk++) {
            float a[TM], b[TN];
            const float4* ap = (const float4*)&As[kk][ty * TM];
            const float4* bp = (const float4*)&Bs[kk][tx * TN];
            float4 a0 = ap[0], a1 = ap[1];
            float4 b0 = bp[0], b1v = bp[1];
            a[0]=a0.x; a[1]=a0.y; a[2]=a0.z; a[3]=a0.w;
            a[4]=a1.x; a[5]=a1.y; a[6]=a1.z; a[7]=a1.w;
            b[0]=b0.x; b[1]=b0.y; b[2]=b0.z; b[3]=b0.w;
            b[4]=b1v.x; b[5]=b1v.y; b[6]=b1v.z; b[7]=b1v.w;
            #pragma unroll
            for (int i = 0; i < TM; i++)
                #pragma unroll
                for (int j = 0; j < TN; j++)
                    acc[i][j] += a[i] * b[j];
        }
        Aptr += BKq;
        Bptr += BKq;
    }

    int n0 = block_n + tx * TN;
    #pragma unroll
    for (int i = 0; i < TM; i++) {
        int m = block_m + ty * TM + i;
        float v[TN];
        #pragma unroll
        for (int j = 0; j < TN; j++) {
            float x = acc[i][j];
            int n = n0 + j;
            if (MODE == 0) x += g_hgates[(size_t)(m & (Bz - 1)) * GATES + n];
            else           x += bias[n];
            v[j] = x;
        }
        float* dst = (MODE == 0) ? (g_gates + (size_t)m * GATES + n0)
                                 : (g_hid + (size_t)m * K2 + n0);
        ((float4*)dst)[0] = make_float4(v[0], v[1], v[2], v[3]);
        ((float4*)dst)[1] = make_float4(v[4], v[5], v[6], v[7]);
    }
}

// ---------------------------------------------------------------------------
// fp32 -> fp16 conversions
// ---------------------------------------------------------------------------
__global__ void convert_w2_kernel(const float* __restrict__ W2)
{
    size_t i = (size_t)blockIdx.x * blockDim.x + threadIdx.x;  // float4 idx
    float4 x = ((const float4*)W2)[i];
    __half2* d = (__half2*)g_w2h;
    d[i * 2 + 0] = __floats2half2_rn(x.x, x.y);
    d[i * 2 + 1] = __floats2half2_rn(x.z, x.w);
}

__global__ void convert_hid_kernel()
{
    size_t i = (size_t)blockIdx.x * blockDim.x + threadIdx.x;  // float4 idx
    float4 x = ((const float4*)g_hid)[i];
    __half h0 = __float2half_rn(x.x);
    __half h1 = __float2half_rn(x.y);
    __half h2 = __float2half_rn(x.z);
    __half h3 = __float2half_rn(x.w);
    __half l0 = __float2half_rn(x.x - __half2float(h0));
    __half l1 = __float2half_rn(x.y - __half2float(h1));
    __half l2 = __float2half_rn(x.z - __half2float(h2));
    __half l3 = __float2half_rn(x.w - __half2float(h3));
    __half2* dh = (__half2*)g_hidhi;
    __half2* dl = (__half2*)g_hidlo;
    dh[i * 2 + 0] = __halves2half2(h0, h1);
    dh[i * 2 + 1] = __halves2half2(h2, h3);
    dl[i * 2 + 0] = __halves2half2(l0, l1);
    dl[i * 2 + 1] = __halves2half2(l2, l3);
}

// ---------------------------------------------------------------------------
// HMMA logits GEMM: out[b][t][v] = hid @ W2^T + b2, 2-pass fp16 split
// (A = Ahi + Alo in fp16, B = fp16 single; D = Ahi*B + Alo*B in fp32 acc).
// CTA tile 128(m) x 256(n), KC=32, 3-stage cp.async pipeline, one sync/chunk.
// 8 warps in 2(m) x 4(n) grid -> 64x64 warp tiles.
// SMEM rows padded to 40 fp16 (80B) -> conflict-free ldmatrix.
// ---------------------------------------------------------------------------
#define KC 32
#define NROW 40                          // KC + 8 pad, fp16 elems (80 bytes)
#define A_T (128 * NROW * 2)             // 10240 B: one 128x32 tile
#define B_T (256 * NROW * 2)             // 20480 B: one 256x32 tile
#define STAGE (2 * A_T + B_T)            // 40960 B: Ahi, Alo, B
#define NSTAGE 3
#define LOGITS_SMEM (NSTAGE * STAGE)     // 122880 B

__global__ void __launch_bounds__(256, 1)
logits_mma_kernel(const float* __restrict__ b2, float* __restrict__ out)
{
    extern __shared__ char dynsmem[];
    uint32_t smem = smem_u32(dynsmem);

    int tid  = threadIdx.x;
    int wid  = tid >> 5;
    int lane = tid & 31;
    int wm   = wid & 1;                  // warp m index (64 rows)
    int wn   = wid >> 1;                 // warp n index (64 cols)

    int m0 = blockIdx.x * 128;
    int n0 = blockIdx.y * 256;

    // global->smem load assignment
    int ra = tid >> 1;                   // A row 0..127 (2 threads/row)
    int hh = tid & 1;                    // 32B half of the 64B k-chunk
    const char* ah_row = (const char*)(g_hidhi + (size_t)(m0 + ra) * K2);
    const char* al_row = (const char*)(g_hidlo + (size_t)(m0 + ra) * K2);
    int brow = n0 + tid;                 // B row 0..255 (1 thread/row)
    if (brow >= Vz) brow = 0;            // clamp: finite garbage, masked at store
    const char* b_row = (const char*)(g_w2h + (size_t)brow * K2);
    uint32_t a_dst = (uint32_t)ra * 80u + (uint32_t)hh * 32u;
    uint32_t b_dst = (uint32_t)tid * 80u;

    float acc[4][8][4];
    #pragma unroll
    for (int i = 0; i < 4; i++)
        #pragma unroll
        for (int j = 0; j < 8; j++)
            #pragma unroll
            for (int q = 0; q < 4; q++) acc[i][j][q] = 0.f;

    // ldmatrix lane-derived offsets
    int a_lrow = lane & 15;
    int a_koff = (lane >> 4) * 16;       // bytes
    int b_mid  = lane >> 3;
    int b_lrow = lane & 7;
    int b_pair = b_mid >> 1;
    int b_half = b_mid & 1;

    auto load_stage = [&](int s, int kc) {
        uint32_t st = smem + (uint32_t)s * STAGE;
        int go = kc * (KC * 2);          // byte offset into fp16 row
        // A hi/lo: 2 x 16B per tensor per thread
        CP16(st + a_dst,            ah_row + go + hh * 32);
        CP16(st + a_dst + 16,       ah_row + go + hh * 32 + 16);
        CP16(st + A_T + a_dst,      al_row + go + hh * 32);
        CP16(st + A_T + a_dst + 16, al_row + go + hh * 32 + 16);
        // B: 4 x 16B per thread (one full 64B row-chunk)
        uint32_t bb = st + 2 * A_T + b_dst;
        #pragma unroll
        for (int j = 0; j < 4; j++)
            CP16(bb + j * 16, b_row + go + j * 16);
        CP_COMMIT();
    };

    const int NKC = K2 / KC;             // 32
    load_stage(0, 0);
    load_stage(1, 1);

    for (int kc = 0; kc < NKC; kc++) {
        CP_WAIT(1);                      // group kc arrived
        __syncthreads();                 // data visible; buffer (kc+2)%3 free
        if (kc + 2 < NKC) load_stage((kc + 2) % 3, kc + 2);

        uint32_t st = smem + (uint32_t)(kc % 3) * STAGE;
        #pragma unroll
        for (int ks = 0; ks < 2; ks++) {
            uint32_t ahf[4][4], alf[4][4];
            #pragma unroll
            for (int im = 0; im < 4; im++) {
                uint32_t aaddr = st
                    + (uint32_t)(wm * 64 + im * 16 + a_lrow) * 80u
                    + (uint32_t)(ks * 32 + a_koff);
                ldsm4(ahf[im], aaddr);
                ldsm4(alf[im], aaddr + A_T);
            }
            #pragma unroll
            for (int jp = 0; jp < 4; jp++) {
                uint32_t baddr = st + 2 * A_T
                    + (uint32_t)(wn * 64 + (jp * 2 + b_pair) * 8 + b_lrow) * 80u
                    + (uint32_t)(ks * 32 + b_half * 16);
                uint32_t bf[4];
                ldsm4(bf, baddr);
                #pragma unroll
                for (int im = 0; im < 4; im++) {
                    mma16816(acc[im][jp * 2 + 0], ahf[im], bf + 0);
                    mma16816(acc[im][jp * 2 + 1], ahf[im], bf + 2);
                    mma16816(acc[im][jp * 2 + 0], alf[im], bf + 0);
                    mma16816(acc[im][jp * 2 + 1], alf[im], bf + 2);
                }
            }
        }
        // no trailing sync: buffer (kc%3) is only rewritten at iter kc+1,
        // after that iteration's __syncthreads.
    }

    // Epilogue: acc -> out[(b)(t)][v] + b2. Scalar stores (Vz odd).
    int grp = lane >> 2;
    int qid = lane & 3;
    #pragma unroll
    for (int im = 0; im < 4; im++) {
        #pragma unroll
        for (int half = 0; half < 2; half++) {
            int mrow = m0 + wm * 64 + im * 16 + grp + half * 8;
            int bb = mrow & 31;
            int tt = mrow >> 5;
            float* orow = out + ((size_t)bb * Tz + tt) * Vz;
            #pragma unroll
            for (int jf = 0; jf < 8; jf++) {
                int col = n0 + wn * 64 + (jf >> 1) * 16 + (jf & 1) * 8 + qid * 2;
                if (col < Vz) {
                    orow[col] = acc[im][jf][half * 2 + 0] + b2[col];
                    if (col + 1 < Vz)
                        orow[col + 1] = acc[im][jf][half * 2 + 1] + b2[col + 1];
                }
            }
        }
    }
}

// ---------------------------------------------------------------------------
// Launch
// ---------------------------------------------------------------------------
extern "C" void kernel_launch(void* const* d_in, const int* in_sizes, int n_in,
                              void* d_out, int out_size)
{
    const float* features = (const float*)d_in[0];
    const int*   captions = (const int*)d_in[1];
    const float* emb      = (const float*)d_in[2];
    const float* W_ih     = (const float*)d_in[3];
    const float* W_hh     = (const float*)d_in[4];
    const float* b_ih     = (const float*)d_in[5];
    const float* b_hh     = (const float*)d_in[6];
    const float* W1       = (const float*)d_in[7];
    const float* b1       = (const float*)d_in[8];
    const float* W2       = (const float*)d_in[9];
    const float* b2       = (const float*)d_in[10];
    float* out = (float*)d_out;

    cudaFuncSetAttribute(logits_mma_kernel,
                         cudaFuncAttributeMaxDynamicSharedMemorySize, LOGITS_SMEM);

    // W2 fp16 conversion (independent; overlaps the front-end)
    convert_w2_kernel<<<(int)(((size_t)Vz * K2 / 4) / 256), 256>>>(W2);

    // 1) gather shifted embeddings
    gather_kernel<<<Mz, Ez / 4>>>(captions, emb);

    // 2) h_gates (+ both biases)
    hgates_kernel<<<(Bz * GATES + 255) / 256, 256>>>(features, W_hh, b_ih, b_hh);

    // 3) gates GEMM (2048 x 2048 x 256) + h_gates
    {
        dim3 grid(GATES / BN, Mz / BM);
        gemm_nt_kernel<0><<<grid, 256>>>(W_ih, nullptr, Mz, GATES, Ez);
    }

    // 4) LSTM scan
    scan_kernel<<<(Bz * Hz + 255) / 256, 256>>>();

    // 5) hid GEMM (2048 x 1024 x 512) + b1
    {
        dim3 grid(K2 / BN, Mz / BM);
        gemm_nt_kernel<1><<<grid, 256>>>(W1, b1, Mz, K2, Hz);
    }

    // 6) hid -> fp16 hi/lo
    convert_hid_kernel<<<(int)(((size_t)Mz * K2 / 4) / 256), 256>>>();

    // 7) HMMA logits GEMM (2048 x 50257 x 1024) + b2, 2-pass fp16 split
    {
        dim3 grid(Mz / 128, (Vz + 255) / 256);  // (16, 197)
        logits_mma_kernel<<<grid, 256, LOGITS_SMEM>>>(b2, out);
    }
}

// round 8
// speedup vs baseline: 3.8298x; 1.3144x over previous
#include <cuda_runtime.h>
#include <cuda_bf16.h>
#include <cuda_fp16.h>
#include <math.h>
#include <stdint.h>

// Problem constants
#define Bz 32
#define Tz 64
#define Vz 50257
#define Ez 256
#define Hz 512
#define GATES 2048          // 4*H
#define Mz 2048             // T*B
#define K2 1024             // 2*H

// ---------------------------------------------------------------------------
// Scratch (static device allocations only)
// ---------------------------------------------------------------------------
__device__ float g_xseq[Mz * Ez];
__device__ float g_hgates[Bz * GATES];
__device__ float g_gates[(size_t)Mz * GATES];
__device__ float g_hs[(size_t)Mz * Hz];

// fp16 operands for the 1-pass logits GEMM
__device__ __half g_w2h[(size_t)Vz * K2];    // ~103 MB, W2 rounded to fp16
__device__ __half g_hidh[(size_t)Mz * K2];   // 4 MB, hid rounded to fp16

// ---------------------------------------------------------------------------
// PTX helpers (base PTX only — NO tcgen05; harness assembles for sm_103 base)
// ---------------------------------------------------------------------------
__device__ __forceinline__ uint32_t smem_u32(const void* p) {
    uint32_t a;
    asm("{ .reg .u64 t; cvta.to.shared.u64 t, %1; cvt.u32.u64 %0, t; }"
        : "=r"(a) : "l"(p));
    return a;
}
#define CP16(dst, src) \
    asm volatile("cp.async.cg.shared.global [%0], [%1], 16;" :: "r"(dst), "l"(src) : "memory")
#define CP_COMMIT()  asm volatile("cp.async.commit_group;" ::: "memory")
#define CP_WAIT(n)   asm volatile("cp.async.wait_group %0;" :: "n"(n) : "memory")

__device__ __forceinline__ void ldsm4(uint32_t* r, uint32_t addr) {
    asm volatile("ldmatrix.sync.aligned.m8n8.x4.shared.b16 {%0,%1,%2,%3}, [%4];"
                 : "=r"(r[0]), "=r"(r[1]), "=r"(r[2]), "=r"(r[3]) : "r"(addr));
}
__device__ __forceinline__ void mma16816(float* c, const uint32_t* a, const uint32_t* b) {
    asm volatile("mma.sync.aligned.m16n8k16.row.col.f32.f16.f16.f32 "
                 "{%0,%1,%2,%3}, {%4,%5,%6,%7}, {%8,%9}, {%0,%1,%2,%3};"
                 : "+f"(c[0]), "+f"(c[1]), "+f"(c[2]), "+f"(c[3])
                 : "r"(a[0]), "r"(a[1]), "r"(a[2]), "r"(a[3]),
                   "r"(b[0]), "r"(b[1]));
}

// ---------------------------------------------------------------------------
// Kernel 1: gather shifted caption embeddings.
// ---------------------------------------------------------------------------
__global__ void gather_kernel(const int* __restrict__ captions,
                              const float* __restrict__ emb)
{
    int m = blockIdx.x;
    int t = m / Bz;
    int b = m % Bz;
    int src_t = (t == 0) ? 0 : (t - 1);
    int token = captions[b * Tz + src_t];
    const float4* src = (const float4*)(emb + (size_t)token * Ez);
    float4* dst = (float4*)(g_xseq + (size_t)m * Ez);
    dst[threadIdx.x] = src[threadIdx.x];
}

// ---------------------------------------------------------------------------
// Kernel 2: h_gates
// ---------------------------------------------------------------------------
__global__ void hgates_kernel(const float* __restrict__ features,
                              const float* __restrict__ W_hh,
                              const float* __restrict__ b_ih,
                              const float* __restrict__ b_hh)
{
    int idx = blockIdx.x * blockDim.x + threadIdx.x;
    if (idx >= Bz * GATES) return;
    int b = idx / GATES;
    int g = idx % GATES;
    const float4* w = (const float4*)(W_hh + (size_t)g * Hz);
    const float4* f = (const float4*)(features + (size_t)b * Hz);
    float s = b_ih[g] + b_hh[g];
    #pragma unroll 4
    for (int k = 0; k < Hz / 4; k++) {
        float4 wv = w[k];
        float4 fv = f[k];
        s += fv.x * wv.x + fv.y * wv.y + fv.z * wv.z + fv.w * wv.w;
    }
    g_hgates[idx] = s;
}

// ---------------------------------------------------------------------------
// Kernel 3: elementwise LSTM scan, software-pipelined (prefetch t+1 gates).
// ---------------------------------------------------------------------------
__global__ void scan_kernel()
{
    int idx = blockIdx.x * blockDim.x + threadIdx.x;
    if (idx >= Bz * Hz) return;
    int b = idx >> 9;
    int h = idx & (Hz - 1);
    float c = 0.f;

    const float* g0 = g_gates + (size_t)b * GATES;   // t = 0 row
    float ni = g0[h];
    float nf = g0[h + Hz];
    float ng = g0[h + 2 * Hz];
    float no = g0[h + 3 * Hz];

    for (int t = 0; t < Tz; t++) {
        float gi = ni, gf = nf, gg = ng, go = no;
        if (t + 1 < Tz) {
            const float* gn = g_gates + (size_t)((t + 1) * Bz + b) * GATES;
            ni = gn[h];
            nf = gn[h + Hz];
            ng = gn[h + 2 * Hz];
            no = gn[h + 3 * Hz];
        }
        float si = 1.f / (1.f + expf(-gi));
        float sf = 1.f / (1.f + expf(-gf));
        float so = 1.f / (1.f + expf(-go));
        c = sf * c + si * tanhf(gg);
        g_hs[(size_t)(t * Bz + b) * Hz + h] = so * tanhf(c);
    }
}

// ---------------------------------------------------------------------------
// SIMT GEMM for the two small GEMMs.
// MODE 0: gates = xseq @ W_ih^T + h_gates   -> g_gates (fp32)
// MODE 1: hid   = hs @ W1^T + b1            -> g_hidh (fp16, GEMM-fused cvt)
// ---------------------------------------------------------------------------
#define BM 128
#define BN 128
#define BKq 8
#define TM 8
#define TN 8

template <int MODE>
__global__ void __launch_bounds__(256)
gemm_nt_kernel(const float* __restrict__ Bm,
               const float* __restrict__ bias,
               int M, int N, int K)
{
    __shared__ float As[BKq][BM];
    __shared__ float Bs[BKq][BN];

    const float* A = (MODE == 0) ? g_xseq : g_hs;

    int block_m = blockIdx.y * BM;
    int block_n = blockIdx.x * BN;
    int tid = threadIdx.x;

    int lr = tid >> 1;
    int lk = (tid & 1) * 4;

    const float* Aptr = A + (size_t)(block_m + lr) * K + lk;
    const float* Bptr = Bm + (size_t)(block_n + lr) * K + lk;

    float acc[TM][TN];
    #pragma unroll
    for (int i = 0; i < TM; i++)
        #pragma unroll
        for (int j = 0; j < TN; j++) acc[i][j] = 0.f;

    int tx = tid & 15;
    int ty = tid >> 4;

    for (int k0 = 0; k0 < K; k0 += BKq) {
        float4 av = *(const float4*)Aptr;
        float4 bv = *(const float4*)Bptr;
        __syncthreads();
        As[lk + 0][lr] = av.x; As[lk + 1][lr] = av.y;
        As[lk + 2][lr] = av.z; As[lk + 3][lr] = av.w;
        Bs[lk + 0][lr] = bv.x; Bs[lk + 1][lr] = bv.y;
        Bs[lk + 2][lr] = bv.z; Bs[lk + 3][lr] = bv.w;
        __syncthreads();

        #pragma unroll
        for (int kk = 0; kk < BKq; kk++) {
            float a[TM], b[TN];
            const float4* ap = (const float4*)&As[kk][ty * TM];
            const float4* bp = (const float4*)&Bs[kk][tx * TN];
            float4 a0 = ap[0], a1 = ap[1];
            float4 b0 = bp[0], b1v = bp[1];
            a[0]=a0.x; a[1]=a0.y; a[2]=a0.z; a[3]=a0.w;
            a[4]=a1.x; a[5]=a1.y; a[6]=a1.z; a[7]=a1.w;
            b[0]=b0.x; b[1]=b0.y; b[2]=b0.z; b[3]=b0.w;
            b[4]=b1v.x; b[5]=b1v.y; b[6]=b1v.z; b[7]=b1v.w;
            #pragma unroll
            for (int i = 0; i < TM; i++)
                #pragma unroll
                for (int j = 0; j < TN; j++)
                    acc[i][j] += a[i] * b[j];
        }
        Aptr += BKq;
        Bptr += BKq;
    }

    int n0 = block_n + tx * TN;
    #pragma unroll
    for (int i = 0; i < TM; i++) {
        int m = block_m + ty * TM + i;
        float v[TN];
        #pragma unroll
        for (int j = 0; j < TN; j++) {
            float x = acc[i][j];
            int n = n0 + j;
            if (MODE == 0) x += g_hgates[(size_t)(m & (Bz - 1)) * GATES + n];
            else           x += bias[n];
            v[j] = x;
        }
        if (MODE == 0) {
            float* dst = g_gates + (size_t)m * GATES + n0;
            ((float4*)dst)[0] = make_float4(v[0], v[1], v[2], v[3]);
            ((float4*)dst)[1] = make_float4(v[4], v[5], v[6], v[7]);
        } else {
            // fused fp32 -> fp16: 8 halves = 16B (n0 multiple of 8 -> aligned)
            __half2 p0 = __floats2half2_rn(v[0], v[1]);
            __half2 p1 = __floats2half2_rn(v[2], v[3]);
            __half2 p2 = __floats2half2_rn(v[4], v[5]);
            __half2 p3 = __floats2half2_rn(v[6], v[7]);
            uint4 pack;
            pack.x = *(uint32_t*)&p0;
            pack.y = *(uint32_t*)&p1;
            pack.z = *(uint32_t*)&p2;
            pack.w = *(uint32_t*)&p3;
            *(uint4*)(g_hidh + (size_t)m * K2 + n0) = pack;
        }
    }
}

// ---------------------------------------------------------------------------
// fp32 -> fp16 conversion for W2
// ---------------------------------------------------------------------------
__global__ void convert_w2_kernel(const float* __restrict__ W2)
{
    size_t i = (size_t)blockIdx.x * blockDim.x + threadIdx.x;  // float4 idx
    float4 x = ((const float4*)W2)[i];
    __half2* d = (__half2*)g_w2h;
    d[i * 2 + 0] = __floats2half2_rn(x.x, x.y);
    d[i * 2 + 1] = __floats2half2_rn(x.z, x.w);
}

// ---------------------------------------------------------------------------
// HMMA logits GEMM: out[b][t][v] = hid @ W2^T + b2, 1-pass fp16.
// CTA tile 128(m) x 256(n), KC=32, 3-stage cp.async pipeline, one sync/chunk.
// 8 warps in 2(m) x 4(n) grid -> 64x64 warp tiles.
// SMEM rows padded to 40 fp16 (80B) -> conflict-free ldmatrix.
// ---------------------------------------------------------------------------
#define KC 32
#define NROW 40                          // KC + 8 pad, fp16 elems (80 bytes)
#define A_T (128 * NROW * 2)             // 10240 B: one 128x32 tile
#define B_T (256 * NROW * 2)             // 20480 B: one 256x32 tile
#define STAGE (A_T + B_T)                // 30720 B: A, B
#define NSTAGE 3
#define LOGITS_SMEM (NSTAGE * STAGE)     // 92160 B

__global__ void __launch_bounds__(256, 1)
logits_mma_kernel(const float* __restrict__ b2, float* __restrict__ out)
{
    extern __shared__ char dynsmem[];
    uint32_t smem = smem_u32(dynsmem);

    int tid  = threadIdx.x;
    int wid  = tid >> 5;
    int lane = tid & 31;
    int wm   = wid & 1;                  // warp m index (64 rows)
    int wn   = wid >> 1;                 // warp n index (64 cols)

    int m0 = blockIdx.x * 128;
    int n0 = blockIdx.y * 256;

    // global->smem load assignment
    int ra = tid >> 1;                   // A row 0..127 (2 threads/row)
    int hh = tid & 1;                    // 32B half of the 64B k-chunk
    const char* a_row = (const char*)(g_hidh + (size_t)(m0 + ra) * K2);
    int brow = n0 + tid;                 // B row 0..255 (1 thread/row)
    if (brow >= Vz) brow = 0;            // clamp: finite garbage, masked at store
    const char* b_row = (const char*)(g_w2h + (size_t)brow * K2);
    uint32_t a_dst = (uint32_t)ra * 80u + (uint32_t)hh * 32u;
    uint32_t b_dst = (uint32_t)tid * 80u;

    float acc[4][8][4];
    #pragma unroll
    for (int i = 0; i < 4; i++)
        #pragma unroll
        for (int j = 0; j < 8; j++)
            #pragma unroll
            for (int q = 0; q < 4; q++) acc[i][j][q] = 0.f;

    // ldmatrix lane-derived offsets
    int a_lrow = lane & 15;
    int a_koff = (lane >> 4) * 16;       // bytes
    int b_mid  = lane >> 3;
    int b_lrow = lane & 7;
    int b_pair = b_mid >> 1;
    int b_half = b_mid & 1;

    auto load_stage = [&](int s, int kc) {
        uint32_t st = smem + (uint32_t)s * STAGE;
        int go = kc * (KC * 2);          // byte offset into fp16 row
        // A: 2 x 16B per thread
        CP16(st + a_dst,      a_row + go + hh * 32);
        CP16(st + a_dst + 16, a_row + go + hh * 32 + 16);
        // B: 4 x 16B per thread (one full 64B row-chunk)
        uint32_t bb = st + A_T + b_dst;
        #pragma unroll
        for (int j = 0; j < 4; j++)
            CP16(bb + j * 16, b_row + go + j * 16);
        CP_COMMIT();
    };

    const int NKC = K2 / KC;             // 32
    load_stage(0, 0);
    load_stage(1, 1);

    for (int kc = 0; kc < NKC; kc++) {
        CP_WAIT(1);                      // group kc arrived
        __syncthreads();                 // data visible; buffer (kc+2)%3 free
        if (kc + 2 < NKC) load_stage((kc + 2) % 3, kc + 2);

        uint32_t st = smem + (uint32_t)(kc % 3) * STAGE;
        #pragma unroll
        for (int ks = 0; ks < 2; ks++) {
            uint32_t af[4][4];
            #pragma unroll
            for (int im = 0; im < 4; im++) {
                uint32_t aaddr = st
                    + (uint32_t)(wm * 64 + im * 16 + a_lrow) * 80u
                    + (uint32_t)(ks * 32 + a_koff);
                ldsm4(af[im], aaddr);
            }
            #pragma unroll
            for (int jp = 0; jp < 4; jp++) {
                uint32_t baddr = st + A_T
                    + (uint32_t)(wn * 64 + (jp * 2 + b_pair) * 8 + b_lrow) * 80u
                    + (uint32_t)(ks * 32 + b_half * 16);
                uint32_t bf[4];
                ldsm4(bf, baddr);
                #pragma unroll
                for (int im = 0; im < 4; im++) {
                    mma16816(acc[im][jp * 2 + 0], af[im], bf + 0);
                    mma16816(acc[im][jp * 2 + 1], af[im], bf + 2);
                }
            }
        }
        // no trailing sync: buffer (kc%3) is only rewritten at iter kc+1,
        // after that iteration's __syncthreads.
    }

    // Epilogue: acc -> out[(b)(t)][v] + b2. Scalar stores (Vz odd).
    int grp = lane >> 2;
    int qid = lane & 3;
    #pragma unroll
    for (int im = 0; im < 4; im++) {
        #pragma unroll
        for (int half = 0; half < 2; half++) {
            int mrow = m0 + wm * 64 + im * 16 + grp + half * 8;
            int bb = mrow & 31;
            int tt = mrow >> 5;
            float* orow = out + ((size_t)bb * Tz + tt) * Vz;
            #pragma unroll
            for (int jf = 0; jf < 8; jf++) {
                int col = n0 + wn * 64 + (jf >> 1) * 16 + (jf & 1) * 8 + qid * 2;
                if (col < Vz) {
                    orow[col] = acc[im][jf][half * 2 + 0] + b2[col];
                    if (col + 1 < Vz)
                        orow[col + 1] = acc[im][jf][half * 2 + 1] + b2[col + 1];
                }
            }
        }
    }
}

// ---------------------------------------------------------------------------
// Launch
// ---------------------------------------------------------------------------
extern "C" void kernel_launch(void* const* d_in, const int* in_sizes, int n_in,
                              void* d_out, int out_size)
{
    const float* features = (const float*)d_in[0];
    const int*   captions = (const int*)d_in[1];
    const float* emb      = (const float*)d_in[2];
    const float* W_ih     = (const float*)d_in[3];
    const float* W_hh     = (const float*)d_in[4];
    const float* b_ih     = (const float*)d_in[5];
    const float* b_hh     = (const float*)d_in[6];
    const float* W1       = (const float*)d_in[7];
    const float* b1       = (const float*)d_in[8];
    const float* W2       = (const float*)d_in[9];
    const float* b2       = (const float*)d_in[10];
    float* out = (float*)d_out;

    cudaFuncSetAttribute(logits_mma_kernel,
                         cudaFuncAttributeMaxDynamicSharedMemorySize, LOGITS_SMEM);

    // W2 fp16 conversion (independent; overlaps the front-end)
    convert_w2_kernel<<<(int)(((size_t)Vz * K2 / 4) / 256), 256>>>(W2);

    // 1) gather shifted embeddings
    gather_kernel<<<Mz, Ez / 4>>>(captions, emb);

    // 2) h_gates (+ both biases)
    hgates_kernel<<<(Bz * GATES + 255) / 256, 256>>>(features, W_hh, b_ih, b_hh);

    // 3) gates GEMM (2048 x 2048 x 256) + h_gates
    {
        dim3 grid(GATES / BN, Mz / BM);
        gemm_nt_kernel<0><<<grid, 256>>>(W_ih, nullptr, Mz, GATES, Ez);
    }

    // 4) LSTM scan
    scan_kernel<<<(Bz * Hz + 255) / 256, 256>>>();

    // 5) hid GEMM (2048 x 1024 x 512) + b1 -> fp16 directly
    {
        dim3 grid(K2 / BN, Mz / BM);
        gemm_nt_kernel<1><<<grid, 256>>>(W1, b1, Mz, K2, Hz);
    }

    // 6) HMMA logits GEMM (2048 x 50257 x 1024) + b2, 1-pass fp16
    {
        dim3 grid(Mz / 128, (Vz + 255) / 256);  // (16, 197)
        logits_mma_kernel<<<grid, 256, LOGITS_SMEM>>>(b2, out);
    }
}

// round 9
// speedup vs baseline: 3.9649x; 1.0353x over previous
#include <cuda_runtime.h>
#include <cuda_bf16.h>
#include <cuda_fp16.h>
#include <math.h>
#include <stdint.h>

// Problem constants
#define Bz 32
#define Tz 64
#define Vz 50257
#define Ez 256
#define Hz 512
#define GATES 2048          // 4*H
#define Mz 2048             // T*B
#define K2 1024             // 2*H

// ---------------------------------------------------------------------------
// Scratch (static device allocations only)
// ---------------------------------------------------------------------------
__device__ float g_xseq[Mz * Ez];
__device__ float g_hgates[Bz * GATES];
__device__ float g_gates[(size_t)Mz * GATES];
__device__ float g_hs[(size_t)Mz * Hz];

// fp16 operands for the 1-pass logits GEMM
__device__ __half g_w2h[(size_t)Vz * K2];    // ~103 MB, W2 rounded to fp16
__device__ __half g_hidh[(size_t)Mz * K2];   // 4 MB, hid rounded to fp16

// ---------------------------------------------------------------------------
// PTX helpers (base PTX only — NO tcgen05; harness assembles for sm_103 base)
// ---------------------------------------------------------------------------
__device__ __forceinline__ uint32_t smem_u32(const void* p) {
    uint32_t a;
    asm("{ .reg .u64 t; cvta.to.shared.u64 t, %1; cvt.u32.u64 %0, t; }"
        : "=r"(a) : "l"(p));
    return a;
}
#define CP16(dst, src) \
    asm volatile("cp.async.cg.shared.global [%0], [%1], 16;" :: "r"(dst), "l"(src) : "memory")
#define CP_COMMIT()  asm volatile("cp.async.commit_group;" ::: "memory")
#define CP_WAIT(n)   asm volatile("cp.async.wait_group %0;" :: "n"(n) : "memory")

__device__ __forceinline__ void ldsm4(uint32_t* r, uint32_t addr) {
    asm volatile("ldmatrix.sync.aligned.m8n8.x4.shared.b16 {%0,%1,%2,%3}, [%4];"
                 : "=r"(r[0]), "=r"(r[1]), "=r"(r[2]), "=r"(r[3]) : "r"(addr));
}
__device__ __forceinline__ void mma16816(float* c, const uint32_t* a, const uint32_t* b) {
    asm volatile("mma.sync.aligned.m16n8k16.row.col.f32.f16.f16.f32 "
                 "{%0,%1,%2,%3}, {%4,%5,%6,%7}, {%8,%9}, {%0,%1,%2,%3};"
                 : "+f"(c[0]), "+f"(c[1]), "+f"(c[2]), "+f"(c[3])
                 : "r"(a[0]), "r"(a[1]), "r"(a[2]), "r"(a[3]),
                   "r"(b[0]), "r"(b[1]));
}

// ---------------------------------------------------------------------------
// Kernel 1 (launch #1): fused prep — gather shifted embeddings + h_gates.
// Blocks [0, 512): gather.  Blocks [512, 768): h_gates.
// ---------------------------------------------------------------------------
__global__ void __launch_bounds__(256)
prep_kernel(const int* __restrict__ captions,
            const float* __restrict__ emb,
            const float* __restrict__ features,
            const float* __restrict__ W_hh,
            const float* __restrict__ b_ih,
            const float* __restrict__ b_hh)
{
    int bid = blockIdx.x;
    if (bid < 512) {
        // gather: one float4 per thread; 64 float4 per row
        int i = bid * 256 + threadIdx.x;       // 0 .. 131071
        int m = i >> 6;
        int c = i & 63;
        int t = m / Bz;
        int b = m % Bz;
        int src_t = (t == 0) ? 0 : (t - 1);
        int token = captions[b * Tz + src_t];
        ((float4*)g_xseq)[i] =
            ((const float4*)(emb + (size_t)token * Ez))[c];
    } else {
        int idx = (bid - 512) * 256 + threadIdx.x;   // 0 .. 65535
        int b = idx / GATES;
        int g = idx % GATES;
        const float4* w = (const float4*)(W_hh + (size_t)g * Hz);
        const float4* f = (const float4*)(features + (size_t)b * Hz);
        float s = b_ih[g] + b_hh[g];
        #pragma unroll 4
        for (int k = 0; k < Hz / 4; k++) {
            float4 wv = w[k];
            float4 fv = f[k];
            s += fv.x * wv.x + fv.y * wv.y + fv.z * wv.z + fv.w * wv.w;
        }
        g_hgates[idx] = s;
    }
}

// ---------------------------------------------------------------------------
// Kernel (launch #3): elementwise LSTM scan, software-pipelined.
// ---------------------------------------------------------------------------
__global__ void scan_kernel()
{
    int idx = blockIdx.x * blockDim.x + threadIdx.x;
    if (idx >= Bz * Hz) return;
    int b = idx >> 9;
    int h = idx & (Hz - 1);
    float c = 0.f;

    const float* g0 = g_gates + (size_t)b * GATES;   // t = 0 row
    float ni = g0[h];
    float nf = g0[h + Hz];
    float ng = g0[h + 2 * Hz];
    float no = g0[h + 3 * Hz];

    for (int t = 0; t < Tz; t++) {
        float gi = ni, gf = nf, gg = ng, go = no;
        if (t + 1 < Tz) {
            const float* gn = g_gates + (size_t)((t + 1) * Bz + b) * GATES;
            ni = gn[h];
            nf = gn[h + Hz];
            ng = gn[h + 2 * Hz];
            no = gn[h + 3 * Hz];
        }
        float si = 1.f / (1.f + expf(-gi));
        float sf = 1.f / (1.f + expf(-gf));
        float so = 1.f / (1.f + expf(-go));
        c = sf * c + si * tanhf(gg);
        g_hs[(size_t)(t * Bz + b) * Hz + h] = so * tanhf(c);
    }
}

// ---------------------------------------------------------------------------
// SIMT GEMM for the two small GEMMs (launches #2, #4).
// MODE 0: gates = xseq @ W_ih^T + h_gates   -> g_gates (fp32)
// MODE 1: hid   = hs @ W1^T + b1            -> g_hidh (fp16, GEMM-fused cvt)
// ---------------------------------------------------------------------------
#define BM 128
#define BN 128
#define BKq 8
#define TM 8
#define TN 8

template <int MODE>
__global__ void __launch_bounds__(256)
gemm_nt_kernel(const float* __restrict__ Bm,
               const float* __restrict__ bias,
               int M, int N, int K)
{
    __shared__ float As[BKq][BM];
    __shared__ float Bs[BKq][BN];

    const float* A = (MODE == 0) ? g_xseq : g_hs;

    int block_m = blockIdx.y * BM;
    int block_n = blockIdx.x * BN;
    int tid = threadIdx.x;

    int lr = tid >> 1;
    int lk = (tid & 1) * 4;

    const float* Aptr = A + (size_t)(block_m + lr) * K + lk;
    const float* Bptr = Bm + (size_t)(block_n + lr) * K + lk;

    float acc[TM][TN];
    #pragma unroll
    for (int i = 0; i < TM; i++)
        #pragma unroll
        for (int j = 0; j < TN; j++) acc[i][j] = 0.f;

    int tx = tid & 15;
    int ty = tid >> 4;

    for (int k0 = 0; k0 < K; k0 += BKq) {
        float4 av = *(const float4*)Aptr;
        float4 bv = *(const float4*)Bptr;
        __syncthreads();
        As[lk + 0][lr] = av.x; As[lk + 1][lr] = av.y;
        As[lk + 2][lr] = av.z; As[lk + 3][lr] = av.w;
        Bs[lk + 0][lr] = bv.x; Bs[lk + 1][lr] = bv.y;
        Bs[lk + 2][lr] = bv.z; Bs[lk + 3][lr] = bv.w;
        __syncthreads();

        #pragma unroll
        for (int kk = 0; kk < BKq; kk++) {
            float a[TM], b[TN];
            const float4* ap = (const float4*)&As[kk][ty * TM];
            const float4* bp = (const float4*)&Bs[kk][tx * TN];
            float4 a0 = ap[0], a1 = ap[1];
            float4 b0 = bp[0], b1v = bp[1];
            a[0]=a0.x; a[1]=a0.y; a[2]=a0.z; a[3]=a0.w;
            a[4]=a1.x; a[5]=a1.y; a[6]=a1.z; a[7]=a1.w;
            b[0]=b0.x; b[1]=b0.y; b[2]=b0.z; b[3]=b0.w;
            b[4]=b1v.x; b[5]=b1v.y; b[6]=b1v.z; b[7]=b1v.w;
            #pragma unroll
            for (int i = 0; i < TM; i++)
                #pragma unroll
                for (int j = 0; j < TN; j++)
                    acc[i][j] += a[i] * b[j];
        }
        Aptr += BKq;
        Bptr += BKq;
    }

    int n0 = block_n + tx * TN;
    #pragma unroll
    for (int i = 0; i < TM; i++) {
        int m = block_m + ty * TM + i;
        float v[TN];
        #pragma unroll
        for (int j = 0; j < TN; j++) {
            float x = acc[i][j];
            int n = n0 + j;
            if (MODE == 0) x += g_hgates[(size_t)(m & (Bz - 1)) * GATES + n];
            else           x += bias[n];
            v[j] = x;
        }
        if (MODE == 0) {
            float* dst = g_gates + (size_t)m * GATES + n0;
            ((float4*)dst)[0] = make_float4(v[0], v[1], v[2], v[3]);
            ((float4*)dst)[1] = make_float4(v[4], v[5], v[6], v[7]);
        } else {
            // fused fp32 -> fp16: 8 halves = 16B (n0 multiple of 8 -> aligned)
            __half2 p0 = __floats2half2_rn(v[0], v[1]);
            __half2 p1 = __floats2half2_rn(v[2], v[3]);
            __half2 p2 = __floats2half2_rn(v[4], v[5]);
            __half2 p3 = __floats2half2_rn(v[6], v[7]);
            uint4 pack;
            pack.x = *(uint32_t*)&p0;
            pack.y = *(uint32_t*)&p1;
            pack.z = *(uint32_t*)&p2;
            pack.w = *(uint32_t*)&p3;
            *(uint4*)(g_hidh + (size_t)m * K2 + n0) = pack;
        }
    }
}

// ---------------------------------------------------------------------------
// Kernel (launch #5): fp32 -> fp16 conversion for W2
// ---------------------------------------------------------------------------
__global__ void convert_w2_kernel(const float* __restrict__ W2)
{
    size_t i = (size_t)blockIdx.x * blockDim.x + threadIdx.x;  // float4 idx
    float4 x = ((const float4*)W2)[i];
    __half2* d = (__half2*)g_w2h;
    d[i * 2 + 0] = __floats2half2_rn(x.x, x.y);
    d[i * 2 + 1] = __floats2half2_rn(x.z, x.w);
}

// ---------------------------------------------------------------------------
// Kernel (launch #6): HMMA logits GEMM, 1-pass fp16.
// out[b][t][v] = hid @ W2^T + b2.
// CTA tile 128(m) x 256(n), KC=32, 4-stage cp.async pipeline (wait_group 2),
// one __syncthreads per chunk. 8 warps in 2(m) x 4(n) grid -> 64x64 tiles.
// SMEM rows padded to 40 fp16 (80B) -> conflict-free ldmatrix.
// ---------------------------------------------------------------------------
#define KC 32
#define NROW 40                          // KC + 8 pad, fp16 elems (80 bytes)
#define A_T (128 * NROW * 2)             // 10240 B: one 128x32 tile
#define B_T (256 * NROW * 2)             // 20480 B: one 256x32 tile
#define STAGE (A_T + B_T)                // 30720 B: A, B
#define NSTAGE 4
#define LOGITS_SMEM (NSTAGE * STAGE)     // 122880 B

__global__ void __launch_bounds__(256, 1)
logits_mma_kernel(const float* __restrict__ b2, float* __restrict__ out)
{
    extern __shared__ char dynsmem[];
    uint32_t smem = smem_u32(dynsmem);

    int tid  = threadIdx.x;
    int wid  = tid >> 5;
    int lane = tid & 31;
    int wm   = wid & 1;                  // warp m index (64 rows)
    int wn   = wid >> 1;                 // warp n index (64 cols)

    int m0 = blockIdx.x * 128;
    int n0 = blockIdx.y * 256;

    // global->smem load assignment
    int ra = tid >> 1;                   // A row 0..127 (2 threads/row)
    int hh = tid & 1;                    // 32B half of the 64B k-chunk
    const char* a_row = (const char*)(g_hidh + (size_t)(m0 + ra) * K2);
    int brow = n0 + tid;                 // B row 0..255 (1 thread/row)
    if (brow >= Vz) brow = 0;            // clamp: finite garbage, masked at store
    const char* b_row = (const char*)(g_w2h + (size_t)brow * K2);
    uint32_t a_dst = (uint32_t)ra * 80u + (uint32_t)hh * 32u;
    uint32_t b_dst = (uint32_t)tid * 80u;

    float acc[4][8][4];
    #pragma unroll
    for (int i = 0; i < 4; i++)
        #pragma unroll
        for (int j = 0; j < 8; j++)
            #pragma unroll
            for (int q = 0; q < 4; q++) acc[i][j][q] = 0.f;

    // ldmatrix lane-derived offsets
    int a_lrow = lane & 15;
    int a_koff = (lane >> 4) * 16;       // bytes
    int b_mid  = lane >> 3;
    int b_lrow = lane & 7;
    int b_pair = b_mid >> 1;
    int b_half = b_mid & 1;

    auto load_stage = [&](int s, int kc) {
        uint32_t st = smem + (uint32_t)s * STAGE;
        int go = kc * (KC * 2);          // byte offset into fp16 row
        // A: 2 x 16B per thread
        CP16(st + a_dst,      a_row + go + hh * 32);
        CP16(st + a_dst + 16, a_row + go + hh * 32 + 16);
        // B: 4 x 16B per thread (one full 64B row-chunk)
        uint32_t bb = st + A_T + b_dst;
        #pragma unroll
        for (int j = 0; j < 4; j++)
            CP16(bb + j * 16, b_row + go + j * 16);
        CP_COMMIT();
    };

    const int NKC = K2 / KC;             // 32
    load_stage(0, 0);
    load_stage(1, 1);
    load_stage(2, 2);

    for (int kc = 0; kc < NKC; kc++) {
        CP_WAIT(2);                      // group kc arrived (kc+1, kc+2 fly)
        __syncthreads();                 // data visible; stage (kc+3)%4 free
        if (kc + 3 < NKC) load_stage((kc + 3) % 4, kc + 3);

        uint32_t st = smem + (uint32_t)(kc % 4) * STAGE;
        #pragma unroll
        for (int ks = 0; ks < 2; ks++) {
            uint32_t af[4][4];
            #pragma unroll
            for (int im = 0; im < 4; im++) {
                uint32_t aaddr = st
                    + (uint32_t)(wm * 64 + im * 16 + a_lrow) * 80u
                    + (uint32_t)(ks * 32 + a_koff);
                ldsm4(af[im], aaddr);
            }
            #pragma unroll
            for (int jp = 0; jp < 4; jp++) {
                uint32_t baddr = st + A_T
                    + (uint32_t)(wn * 64 + (jp * 2 + b_pair) * 8 + b_lrow) * 80u
                    + (uint32_t)(ks * 32 + b_half * 16);
                uint32_t bf[4];
                ldsm4(bf, baddr);
                #pragma unroll
                for (int im = 0; im < 4; im++) {
                    mma16816(acc[im][jp * 2 + 0], af[im], bf + 0);
                    mma16816(acc[im][jp * 2 + 1], af[im], bf + 2);
                }
            }
        }
        // no trailing sync: stage (kc%4) is only rewritten at iter kc+1,
        // after that iteration's __syncthreads.
    }

    // Epilogue: acc -> out[(b)(t)][v] + b2. Scalar stores (Vz odd).
    int grp = lane >> 2;
    int qid = lane & 3;
    #pragma unroll
    for (int im = 0; im < 4; im++) {
        #pragma unroll
        for (int half = 0; half < 2; half++) {
            int mrow = m0 + wm * 64 + im * 16 + grp + half * 8;
            int bb = mrow & 31;
            int tt = mrow >> 5;
            float* orow = out + ((size_t)bb * Tz + tt) * Vz;
            #pragma unroll
            for (int jf = 0; jf < 8; jf++) {
                int col = n0 + wn * 64 + (jf >> 1) * 16 + (jf & 1) * 8 + qid * 2;
                if (col < Vz) {
                    orow[col] = acc[im][jf][half * 2 + 0] + b2[col];
                    if (col + 1 < Vz)
                        orow[col + 1] = acc[im][jf][half * 2 + 1] + b2[col + 1];
                }
            }
        }
    }
}

// ---------------------------------------------------------------------------
// Launch: logits is the 6th launch so ncu (-s 5 -c 1) captures it.
// ---------------------------------------------------------------------------
extern "C" void kernel_launch(void* const* d_in, const int* in_sizes, int n_in,
                              void* d_out, int out_size)
{
    const float* features = (const float*)d_in[0];
    const int*   captions = (const int*)d_in[1];
    const float* emb      = (const float*)d_in[2];
    const float* W_ih     = (const float*)d_in[3];
    const float* W_hh     = (const float*)d_in[4];
    const float* b_ih     = (const float*)d_in[5];
    const float* b_hh     = (const float*)d_in[6];
    const float* W1       = (const float*)d_in[7];
    const float* b1       = (const float*)d_in[8];
    const float* W2       = (const float*)d_in[9];
    const float* b2       = (const float*)d_in[10];
    float* out = (float*)d_out;

    cudaFuncSetAttribute(logits_mma_kernel,
                         cudaFuncAttributeMaxDynamicSharedMemorySize, LOGITS_SMEM);

    // #1: fused gather + h_gates
    prep_kernel<<<768, 256>>>(captions, emb, features, W_hh, b_ih, b_hh);

    // #2: gates GEMM (2048 x 2048 x 256) + h_gates
    {
        dim3 grid(GATES / BN, Mz / BM);
        gemm_nt_kernel<0><<<grid, 256>>>(W_ih, nullptr, Mz, GATES, Ez);
    }

    // #3: LSTM scan
    scan_kernel<<<(Bz * Hz + 255) / 256, 256>>>();

    // #4: hid GEMM (2048 x 1024 x 512) + b1 -> fp16 directly
    {
        dim3 grid(K2 / BN, Mz / BM);
        gemm_nt_kernel<1><<<grid, 256>>>(W1, b1, Mz, K2, Hz);
    }

    // #5: W2 fp16 conversion
    convert_w2_kernel<<<(int)(((size_t)Vz * K2 / 4) / 256), 256>>>(W2);

    // #6: HMMA logits GEMM (2048 x 50257 x 1024) + b2, 1-pass fp16
    {
        dim3 grid(Mz / 128, (Vz + 255) / 256);  // (16, 197)
        logits_mma_kernel<<<grid, 256, LOGITS_SMEM>>>(b2, out);
    }
}

// round 11
// speedup vs baseline: 4.1915x; 1.0572x over previous
#include <cuda_runtime.h>
#include <cuda_fp16.h>
#include <math.h>
#include <stdint.h>

// Problem constants
#define Bz 32
#define Tz 64
#define Vz 50257
#define Ez 256
#define Hz 512
#define GATES 2048          // 4*H
#define Mz 2048             // T*B
#define K2 1024             // 2*H

// ---------------------------------------------------------------------------
// Scratch (static device allocations only; referenced ONLY from device code)
// ---------------------------------------------------------------------------
__device__ float  g_hgates[Bz * GATES];            // fp32 features@W_hh^T + biases
__device__ float  g_gates[(size_t)Mz * GATES];     // fp32, INTERLEAVED [m][h*4+gate]
__device__ __half g_xseqh[Mz * Ez];                // fp16 gathered embeddings
__device__ __half g_wihh[GATES * Ez];              // fp16 W_ih
__device__ __half g_w1h[K2 * Hz];                  // fp16 W1
__device__ __half g_hsh[(size_t)Mz * Hz];          // fp16 hidden states
__device__ __half g_w2h[(size_t)Vz * K2];          // fp16 W2 (~103 MB)
__device__ __half g_hidh[(size_t)Mz * K2];         // fp16 hid

// ---------------------------------------------------------------------------
// PTX helpers (base PTX only — NO tcgen05; harness assembles for sm_103 base)
// ---------------------------------------------------------------------------
__device__ __forceinline__ uint32_t smem_u32(const void* p) {
    uint32_t a;
    asm("{ .reg .u64 t; cvta.to.shared.u64 t, %1; cvt.u32.u64 %0, t; }"
        : "=r"(a) : "l"(p));
    return a;
}
#define CP16(dst, src) \
    asm volatile("cp.async.cg.shared.global [%0], [%1], 16;" :: "r"(dst), "l"(src) : "memory")
#define CP_COMMIT()  asm volatile("cp.async.commit_group;" ::: "memory")
#define CP_WAIT(n)   asm volatile("cp.async.wait_group %0;" :: "n"(n) : "memory")

__device__ __forceinline__ void ldsm4(uint32_t* r, uint32_t addr) {
    asm volatile("ldmatrix.sync.aligned.m8n8.x4.shared.b16 {%0,%1,%2,%3}, [%4];"
                 : "=r"(r[0]), "=r"(r[1]), "=r"(r[2]), "=r"(r[3]) : "r"(addr));
}
__device__ __forceinline__ void mma16816(float* c, const uint32_t* a, const uint32_t* b) {
    asm volatile("mma.sync.aligned.m16n8k16.row.col.f32.f16.f16.f32 "
                 "{%0,%1,%2,%3}, {%4,%5,%6,%7}, {%8,%9}, {%0,%1,%2,%3};"
                 : "+f"(c[0]), "+f"(c[1]), "+f"(c[2]), "+f"(c[3])
                 : "r"(a[0]), "r"(a[1]), "r"(a[2]), "r"(a[3]),
                   "r"(b[0]), "r"(b[1]));
}

// ---------------------------------------------------------------------------
// Launch #1: prep — gather emb->fp16, h_gates (fp32), W_ih->fp16, W1->fp16.
// Block bands: [0,512) gather | [512,768) h_gates | [768,1280) W_ih | [1280,1792) W1
// ---------------------------------------------------------------------------
__global__ void __launch_bounds__(256)
prep_kernel(const int* __restrict__ captions,
            const float* __restrict__ emb,
            const float* __restrict__ features,
            const float* __restrict__ W_hh,
            const float* __restrict__ b_ih,
            const float* __restrict__ b_hh,
            const float* __restrict__ W_ih,
            const float* __restrict__ W1)
{
    int bid = blockIdx.x;
    if (bid < 512) {
        int i = bid * 256 + threadIdx.x;       // float4 idx, 0..131071
        int m = i >> 6;
        int c = i & 63;
        int t = m / Bz;
        int b = m % Bz;
        int src_t = (t == 0) ? 0 : (t - 1);
        int token = captions[b * Tz + src_t];
        float4 x = ((const float4*)(emb + (size_t)token * Ez))[c];
        __half2 p0 = __floats2half2_rn(x.x, x.y);
        __half2 p1 = __floats2half2_rn(x.z, x.w);
        uint2 pk = make_uint2(*(uint32_t*)&p0, *(uint32_t*)&p1);
        *(uint2*)(g_xseqh + (size_t)m * Ez + c * 4) = pk;
    } else if (bid < 768) {
        int idx = (bid - 512) * 256 + threadIdx.x;   // 0..65535
        int b = idx / GATES;
        int g = idx % GATES;
        const float4* w = (const float4*)(W_hh + (size_t)g * Hz);
        const float4* f = (const float4*)(features + (size_t)b * Hz);
        float s = b_ih[g] + b_hh[g];
        #pragma unroll 4
        for (int k = 0; k < Hz / 4; k++) {
            float4 wv = w[k];
            float4 fv = f[k];
            s += fv.x * wv.x + fv.y * wv.y + fv.z * wv.z + fv.w * wv.w;
        }
        g_hgates[idx] = s;
    } else if (bid < 1280) {
        int i = (bid - 768) * 256 + threadIdx.x;     // float4 idx into W_ih
        float4 x = ((const float4*)W_ih)[i];
        __half2 p0 = __floats2half2_rn(x.x, x.y);
        __half2 p1 = __floats2half2_rn(x.z, x.w);
        uint2 pk = make_uint2(*(uint32_t*)&p0, *(uint32_t*)&p1);
        *(uint2*)(g_wihh + (size_t)i * 4) = pk;
    } else {
        int i = (bid - 1280) * 256 + threadIdx.x;    // float4 idx into W1
        float4 x = ((const float4*)W1)[i];
        __half2 p0 = __floats2half2_rn(x.x, x.y);
        __half2 p1 = __floats2half2_rn(x.z, x.w);
        uint2 pk = make_uint2(*(uint32_t*)&p0, *(uint32_t*)&p1);
        *(uint2*)(g_w1h + (size_t)i * 4) = pk;
    }
}

// ---------------------------------------------------------------------------
// Launch #3: LSTM scan. Gates are interleaved [m][h*4+gate] -> one float4/step.
// Writes hs as fp16.
// ---------------------------------------------------------------------------
__global__ void scan_kernel()
{
    int idx = blockIdx.x * blockDim.x + threadIdx.x;
    if (idx >= Bz * Hz) return;
    int b = idx >> 9;
    int h = idx & (Hz - 1);
    float c = 0.f;

    float4 nx = *(const float4*)(g_gates + (size_t)b * GATES + h * 4);
    for (int t = 0; t < Tz; t++) {
        float4 gv = nx;
        if (t + 1 < Tz)
            nx = *(const float4*)(g_gates +
                    (size_t)((t + 1) * Bz + b) * GATES + h * 4);
        float si = 1.f / (1.f + expf(-gv.x));
        float sf = 1.f / (1.f + expf(-gv.y));
        float so = 1.f / (1.f + expf(-gv.w));
        c = sf * c + si * tanhf(gv.z);
        g_hsh[(size_t)(t * Bz + b) * Hz + h] = __float2half_rn(so * tanhf(c));
    }
}

// ---------------------------------------------------------------------------
// Launch #5: fp32 -> fp16 conversion for W2
// ---------------------------------------------------------------------------
__global__ void convert_w2_kernel(const float* __restrict__ W2)
{
    size_t i = (size_t)blockIdx.x * blockDim.x + threadIdx.x;  // float4 idx
    float4 x = ((const float4*)W2)[i];
    __half2* d = (__half2*)g_w2h;
    d[i * 2 + 0] = __floats2half2_rn(x.x, x.y);
    d[i * 2 + 1] = __floats2half2_rn(x.z, x.w);
}

// ---------------------------------------------------------------------------
// Unified HMMA GEMM (1-pass fp16, fp32 accum): C = A @ B^T + epilogue.
// A and B are selected from device globals INSIDE the kernel by MODE
// (device globals must never be passed from host code!).
// CTA tile 128(m) x 256(n), KC=32, 4-stage cp.async pipeline, 1 sync/chunk.
// 8 warps in 2(m) x 4(n) grid -> 64x64 warp tiles. Rows padded to 80B.
// MODE 0 (gates):  A=g_xseqh B=g_wihh K=256,  epi += g_hgates[m&31][n],
//                  store fp32 g_gates INTERLEAVED [m][(n&511)*4 + (n>>9)]
// MODE 1 (hid):    A=g_hsh   B=g_w1h  K=512,  epi += b1[n], fp16 g_hidh[m][n]
// MODE 2 (logits): A=g_hidh  B=g_w2h  K=1024, epi += b2[n],
//                  store fp32 out[(m&31)*Tz + m>>5][n], clamp n<Vz
// ---------------------------------------------------------------------------
#define KC 32
#define NROW 40                          // KC + 8 pad, fp16 elems (80 bytes)
#define A_T (128 * NROW * 2)             // 10240 B
#define B_T (256 * NROW * 2)             // 20480 B
#define STAGE (A_T + B_T)                // 30720 B
#define NSTAGE 4
#define MMA_SMEM (NSTAGE * STAGE)        // 122880 B

template <int KDIM, int NB, int MODE>
__global__ void __launch_bounds__(256, 1)
hmma_kernel(const float* __restrict__ bias, float* __restrict__ out)
{
    extern __shared__ char dynsmem[];
    uint32_t smem = smem_u32(dynsmem);

    int tid  = threadIdx.x;
    int wid  = tid >> 5;
    int lane = tid & 31;
    int wm   = wid & 1;
    int wn   = wid >> 1;

    int m0 = blockIdx.x * 128;
    int n0 = blockIdx.y * 256;

    const __half* Asrc = (MODE == 0) ? g_xseqh : (MODE == 1) ? g_hsh : g_hidh;
    const __half* Bsrc = (MODE == 0) ? g_wihh  : (MODE == 1) ? g_w1h : g_w2h;

    int ra = tid >> 1;
    int hh = tid & 1;
    const char* a_row = (const char*)(Asrc + (size_t)(m0 + ra) * KDIM);
    int brow = n0 + tid;
    if (MODE == 2 && brow >= NB) brow = 0;   // clamp (garbage masked at store)
    const char* b_row = (const char*)(Bsrc + (size_t)brow * KDIM);
    uint32_t a_dst = (uint32_t)ra * 80u + (uint32_t)hh * 32u;
    uint32_t b_dst = (uint32_t)tid * 80u;

    float acc[4][8][4];
    #pragma unroll
    for (int i = 0; i < 4; i++)
        #pragma unroll
        for (int j = 0; j < 8; j++)
            #pragma unroll
            for (int q = 0; q < 4; q++) acc[i][j][q] = 0.f;

    int a_lrow = lane & 15;
    int a_koff = (lane >> 4) * 16;
    int b_mid  = lane >> 3;
    int b_lrow = lane & 7;
    int b_pair = b_mid >> 1;
    int b_half = b_mid & 1;

    auto load_stage = [&](int s, int kc) {
        uint32_t st = smem + (uint32_t)s * STAGE;
        int go = kc * (KC * 2);
        CP16(st + a_dst,      a_row + go + hh * 32);
        CP16(st + a_dst + 16, a_row + go + hh * 32 + 16);
        uint32_t bb = st + A_T + b_dst;
        #pragma unroll
        for (int j = 0; j < 4; j++)
            CP16(bb + j * 16, b_row + go + j * 16);
        CP_COMMIT();
    };

    const int NKC = KDIM / KC;
    load_stage(0, 0);
    load_stage(1, 1);
    load_stage(2, 2);

    for (int kc = 0; kc < NKC; kc++) {
        // exact wait: ensures group kc complete even in the commit-free tail
        if (kc + 2 < NKC)      CP_WAIT(2);
        else if (kc + 1 < NKC) CP_WAIT(1);
        else                   CP_WAIT(0);
        __syncthreads();
        if (kc + 3 < NKC) load_stage((kc + 3) % 4, kc + 3);

        uint32_t st = smem + (uint32_t)(kc % 4) * STAGE;
        #pragma unroll
        for (int ks = 0; ks < 2; ks++) {
            uint32_t af[4][4];
            #pragma unroll
            for (int im = 0; im < 4; im++) {
                uint32_t aaddr = st
                    + (uint32_t)(wm * 64 + im * 16 + a_lrow) * 80u
                    + (uint32_t)(ks * 32 + a_koff);
                ldsm4(af[im], aaddr);
            }
            #pragma unroll
            for (int jp = 0; jp < 4; jp++) {
                uint32_t baddr = st + A_T
                    + (uint32_t)(wn * 64 + (jp * 2 + b_pair) * 8 + b_lrow) * 80u
                    + (uint32_t)(ks * 32 + b_half * 16);
                uint32_t bf[4];
                ldsm4(bf, baddr);
                #pragma unroll
                for (int im = 0; im < 4; im++) {
                    mma16816(acc[im][jp * 2 + 0], af[im], bf + 0);
                    mma16816(acc[im][jp * 2 + 1], af[im], bf + 2);
                }
            }
        }
    }

    // Epilogue
    int grp = lane >> 2;
    int qid = lane & 3;
    #pragma unroll
    for (int im = 0; im < 4; im++) {
        #pragma unroll
        for (int half = 0; half < 2; half++) {
            int mrow = m0 + wm * 64 + im * 16 + grp + half * 8;
            #pragma unroll
            for (int jf = 0; jf < 8; jf++) {
                int col = n0 + wn * 64 + (jf >> 1) * 16 + (jf & 1) * 8 + qid * 2;
                float v0 = acc[im][jf][half * 2 + 0];
                float v1 = acc[im][jf][half * 2 + 1];
                if (MODE == 0) {
                    const float* hg = g_hgates + (size_t)(mrow & 31) * GATES;
                    v0 += hg[col];
                    v1 += hg[col + 1];
                    float* gr = g_gates + (size_t)mrow * GATES;
                    gr[(col & 511) * 4 + (col >> 9)] = v0;
                    gr[((col + 1) & 511) * 4 + ((col + 1) >> 9)] = v1;
                } else if (MODE == 1) {
                    v0 += bias[col];
                    v1 += bias[col + 1];
                    __half2 p = __floats2half2_rn(v0, v1);
                    *(__half2*)(g_hidh + (size_t)mrow * K2 + col) = p;
                } else {
                    int bb = mrow & 31;
                    int tt = mrow >> 5;
                    float* orow = out + ((size_t)bb * Tz + tt) * Vz;
                    if (col < NB) {
                        orow[col] = v0 + bias[col];
                        if (col + 1 < NB) orow[col + 1] = v1 + bias[col + 1];
                    }
                }
            }
        }
    }
}

// ---------------------------------------------------------------------------
// Launch
// ---------------------------------------------------------------------------
extern "C" void kernel_launch(void* const* d_in, const int* in_sizes, int n_in,
                              void* d_out, int out_size)
{
    const float* features = (const float*)d_in[0];
    const int*   captions = (const int*)d_in[1];
    const float* emb      = (const float*)d_in[2];
    const float* W_ih     = (const float*)d_in[3];
    const float* W_hh     = (const float*)d_in[4];
    const float* b_ih     = (const float*)d_in[5];
    const float* b_hh     = (const float*)d_in[6];
    const float* W1       = (const float*)d_in[7];
    const float* b1       = (const float*)d_in[8];
    const float* W2       = (const float*)d_in[9];
    const float* b2       = (const float*)d_in[10];
    float* out = (float*)d_out;

    cudaFuncSetAttribute(hmma_kernel<Ez, GATES, 0>,
                         cudaFuncAttributeMaxDynamicSharedMemorySize, MMA_SMEM);
    cudaFuncSetAttribute(hmma_kernel<Hz, K2, 1>,
                         cudaFuncAttributeMaxDynamicSharedMemorySize, MMA_SMEM);
    cudaFuncSetAttribute(hmma_kernel<K2, Vz, 2>,
                         cudaFuncAttributeMaxDynamicSharedMemorySize, MMA_SMEM);

    // #1: prep (gather->fp16, h_gates, W_ih->fp16, W1->fp16)
    prep_kernel<<<1792, 256>>>(captions, emb, features, W_hh, b_ih, b_hh,
                               W_ih, W1);

    // #2: gates GEMM (2048 x 2048 x 256) fp16 HMMA + h_gates, interleaved out
    {
        dim3 grid(Mz / 128, GATES / 256);   // (16, 8)
        hmma_kernel<Ez, GATES, 0><<<grid, 256, MMA_SMEM>>>(nullptr, nullptr);
    }

    // #3: LSTM scan (float4 gates, fp16 hs out)
    scan_kernel<<<(Bz * Hz + 255) / 256, 256>>>();

    // #4: hid GEMM (2048 x 1024 x 512) fp16 HMMA + b1 -> fp16
    {
        dim3 grid(Mz / 128, K2 / 256);      // (16, 4)
        hmma_kernel<Hz, K2, 1><<<grid, 256, MMA_SMEM>>>(b1, nullptr);
    }

    // #5: W2 fp16 conversion
    convert_w2_kernel<<<(int)(((size_t)Vz * K2 / 4) / 256), 256>>>(W2);

    // #6: logits GEMM (2048 x 50257 x 1024) fp16 HMMA + b2
    {
        dim3 grid(Mz / 128, (Vz + 255) / 256);  // (16, 197)
        hmma_kernel<K2, Vz, 2><<<grid, 256, MMA_SMEM>>>(b2, out);
    }
}